// round 12
// baseline (speedup 1.0000x reference)
#include <cuda_runtime.h>
#include <cstdint>

#define NUSERS 100000
#define E 64
#define P 128
#define NSHARD 16
#define MSZ 512
#define WD 64
#define RR 4
#define INSZ 256
#define BB 256
#define SS 128
#define IND 384
#define QO 256

#define MSP 68
#define ESP 20

__device__ float g_pe[BB * P];
__device__ float g_q[(size_t)BB * SS * QO];
__device__ int g_uid[BB];

__global__ void k_uid(const int* __restrict__ u) {
    int s = 2;
#pragma unroll
    for (int i = 0; i < 8; i++)
        if (u[2 * i + 1] != 0) s = 1;
    int b = blockIdx.x * blockDim.x + threadIdx.x;
    if (b < BB) g_uid[b] = u[b * s];
}

__device__ __forceinline__ void msp(float x, uint32_t& h, uint32_t& l) {
    h = __float_as_uint(x) & 0xFFFFE000u;
    l = __float_as_uint(x - __uint_as_float(h));
}
__device__ __forceinline__ void mma8(float d[4], const uint32_t a[4], uint32_t b0, uint32_t b1) {
    asm volatile(
        "mma.sync.aligned.m16n8k8.row.col.f32.tf32.tf32.f32 "
        "{%0,%1,%2,%3}, {%4,%5,%6,%7}, {%8,%9}, {%0,%1,%2,%3};"
        : "+f"(d[0]), "+f"(d[1]), "+f"(d[2]), "+f"(d[3])
        : "r"(a[0]), "r"(a[1]), "r"(a[2]), "r"(a[3]), "r"(b0), "r"(b1));
}
__device__ __forceinline__ uint32_t smem_u32(const void* p) {
    uint32_t a;
    asm("{ .reg .u64 t; cvta.to.shared.u64 t, %1; cvt.u32.u64 %0, t; }" : "=r"(a) : "l"(p));
    return a;
}
__device__ __forceinline__ void cpa16(uint32_t s, const void* g) {
    asm volatile("cp.async.ca.shared.global [%0], [%1], 16;" :: "r"(s), "l"(g));
}
__device__ __forceinline__ void cpcommit() { asm volatile("cp.async.commit_group;"); }
__device__ __forceinline__ void cpwait1() { asm volatile("cp.async.wait_group 1;"); }
__device__ __forceinline__ void cpwait0() { asm volatile("cp.async.wait_group 0;"); }

__global__ void k_pe(const float* __restrict__ tab, const float* __restrict__ Wp,
                     const float* __restrict__ bp) {
    __shared__ float ue[E];
    int b = blockIdx.x;
    int t = threadIdx.x;
    int uid = g_uid[b];
    if (t < E) ue[t] = tab[(size_t)uid * E + t];
    __syncthreads();
    float acc = bp[t];
#pragma unroll
    for (int e = 0; e < E; e++) acc += ue[e] * Wp[e * P + t];
    g_pe[b * P + t] = acc;
}

// --- q = concat(x, pe) @ Wq[sid]; cp.async double-buffered, 8 acc chains ---
__global__ __launch_bounds__(256) void k_qgemm(const float* __restrict__ x,
                                               const float* __restrict__ Wq) {
    __shared__ float As[2][64][36];
    __shared__ float Bs[2][32][68];
    int b = blockIdx.z;
    int n0 = blockIdx.x * 64, m0 = blockIdx.y * 64;
    int sid = ((unsigned)g_uid[b]) % NSHARD;
    const float* Wg = Wq + (size_t)sid * IND * QO;
    int tid = threadIdx.x;
    int lane = tid & 31, warp = tid >> 5;
    int g = lane >> 2, c = lane & 3;
    int wm = warp & 3, wn = warp >> 2;
    const float* xb = x + ((size_t)b * SS + m0) * INSZ;
    const float* pe = g_pe + b * P;
    uint32_t asb = smem_u32(&As[0][0][0]);
    uint32_t bsb = smem_u32(&Bs[0][0][0]);

    float d[2][4][4];
#pragma unroll
    for (int p = 0; p < 2; p++)
#pragma unroll
        for (int i = 0; i < 4; i++)
#pragma unroll
            for (int j = 0; j < 4; j++) d[p][i][j] = 0.f;

#define LOADTILE(t, buf)                                                                  \
    do {                                                                                  \
        int k0_ = (t) * 32;                                                               \
        for (int i = tid; i < 512; i += 256) {                                            \
            int row = i >> 3, k4 = (i & 7) * 4;                                           \
            const float* src = (k0_ < INSZ) ? &xb[row * INSZ + k0_ + k4]                  \
                                            : &pe[k0_ - INSZ + k4];                       \
            cpa16(asb + ((buf) * 64 * 36 + row * 36 + k4) * 4, src);                      \
        }                                                                                 \
        for (int i = tid; i < 512; i += 256) {                                            \
            int kk = i >> 4, n4 = (i & 15) * 4;                                           \
            cpa16(bsb + ((buf) * 32 * 68 + kk * 68 + n4) * 4,                             \
                  &Wg[(size_t)(k0_ + kk) * QO + n0 + n4]);                                \
        }                                                                                 \
    } while (0)

    LOADTILE(0, 0);
    cpcommit();

    for (int t = 0; t < 12; t++) {
        int buf = t & 1;
        if (t < 11) {
            LOADTILE(t + 1, buf ^ 1);
            cpcommit();
            cpwait1();
        } else {
            cpwait0();
        }
        __syncthreads();
#pragma unroll
        for (int ks = 0; ks < 4; ks++) {
            int par = ks & 1;
            uint32_t ah[4], al[4];
            msp(As[buf][wm * 16 + g][ks * 8 + c], ah[0], al[0]);
            msp(As[buf][wm * 16 + g + 8][ks * 8 + c], ah[1], al[1]);
            msp(As[buf][wm * 16 + g][ks * 8 + c + 4], ah[2], al[2]);
            msp(As[buf][wm * 16 + g + 8][ks * 8 + c + 4], ah[3], al[3]);
#pragma unroll
            for (int nt = 0; nt < 4; nt++) {
                int nn = wn * 32 + nt * 8;
                uint32_t bh0, bl0, bh1, bl1;
                msp(Bs[buf][ks * 8 + c][nn + g], bh0, bl0);
                msp(Bs[buf][ks * 8 + c + 4][nn + g], bh1, bl1);
                mma8(d[par][nt], ah, bh0, bh1);
                mma8(d[par][nt], ah, bl0, bl1);
                mma8(d[par][nt], al, bh0, bh1);
            }
        }
        __syncthreads();
    }
    float* qb = g_q + ((size_t)b * SS + m0) * QO + n0;
#pragma unroll
    for (int nt = 0; nt < 4; nt++) {
        int nn = wn * 32 + nt * 8 + 2 * c;
        float2 v01 = {d[0][nt][0] + d[1][nt][0], d[0][nt][1] + d[1][nt][1]};
        float2 v23 = {d[0][nt][2] + d[1][nt][2], d[0][nt][3] + d[1][nt][3]};
        *(float2*)&qb[(size_t)(wm * 16 + g) * QO + nn] = v01;
        *(float2*)&qb[(size_t)(wm * 16 + g + 8) * QO + nn] = v23;
    }
}

// ---------------- flash attention, no-max softmax (scores bounded << 88) ----------------
__global__ __launch_bounds__(256, 2) void k_attn(const float* __restrict__ mem,
                                                 float* __restrict__ out) {
    extern __shared__ float sm[];
    float* qs = sm;
    float* ms = qs + 128 * MSP;
    float* es = ms + 128 * MSP;

    int tid = threadIdx.x;
    int lane = tid & 31, warp = tid >> 5;
    int g = lane >> 2, c = lane & 3;
    int b = blockIdx.y;
    int s0 = blockIdx.x * 32;
    int sid = ((unsigned)g_uid[b]) % NSHARD;
    const float* M = mem + (size_t)sid * MSZ * WD;
    float* ew = es + warp * (16 * ESP);
    int wrow = warp * 16;

    const float* qsrc = g_q + ((size_t)b * SS + s0) * QO;
    for (int i = tid; i < 128 * 16; i += 256) {
        int row = i >> 4, w4 = (i & 15) * 4;
        float4 v = *(const float4*)&qsrc[(size_t)(row >> 2) * QO + (row & 3) * WD + w4];
        *(float4*)&qs[row * MSP + w4] = v;
    }

    uint32_t ah[8][4], al[8][4];
    float acc[8][4];
#pragma unroll
    for (int nt = 0; nt < 8; nt++)
#pragma unroll
        for (int j = 0; j < 4; j++) acc[nt][j] = 0.f;
    float sm0 = 0.f, sm1 = 0.f;

    for (int ch = 0; ch < 4; ch++) {
        for (int i = tid; i < 128 * 16; i += 256) {
            int m = i >> 4, w4 = (i & 15) * 4;
            *(float4*)&ms[m * MSP + w4] = *(const float4*)&M[(size_t)(ch * 128 + m) * WD + w4];
        }
        __syncthreads();
        if (ch == 0) {
#pragma unroll
            for (int k = 0; k < 8; k++) {
                msp(qs[(wrow + g) * MSP + k * 8 + c], ah[k][0], al[k][0]);
                msp(qs[(wrow + g + 8) * MSP + k * 8 + c], ah[k][1], al[k][1]);
                msp(qs[(wrow + g) * MSP + k * 8 + c + 4], ah[k][2], al[k][2]);
                msp(qs[(wrow + g + 8) * MSP + k * 8 + c + 4], ah[k][3], al[k][3]);
            }
        }
        for (int sb = 0; sb < 8; sb++) {
#pragma unroll
            for (int nt2 = 0; nt2 < 2; nt2++) {
                int mc = sb * 16 + nt2 * 8;
                float d0[4] = {0.f, 0.f, 0.f, 0.f};
                float d1[4] = {0.f, 0.f, 0.f, 0.f};
#pragma unroll
                for (int k = 0; k < 8; k += 2) {
                    uint32_t bh0, bl0, bh1, bl1;
                    msp(ms[(mc + g) * MSP + k * 8 + c], bh0, bl0);
                    msp(ms[(mc + g) * MSP + k * 8 + c + 4], bh1, bl1);
                    mma8(d0, ah[k], bh0, bh1);
                    mma8(d0, ah[k], bl0, bl1);
                    mma8(d0, al[k], bh0, bh1);
                    uint32_t ch0, cl0, ch1, cl1;
                    msp(ms[(mc + g) * MSP + (k + 1) * 8 + c], ch0, cl0);
                    msp(ms[(mc + g) * MSP + (k + 1) * 8 + c + 4], ch1, cl1);
                    mma8(d1, ah[k + 1], ch0, ch1);
                    mma8(d1, ah[k + 1], cl0, cl1);
                    mma8(d1, al[k + 1], ch0, ch1);
                }
                float e0 = __expf(d0[0] + d1[0]);
                float e1 = __expf(d0[1] + d1[1]);
                float e2 = __expf(d0[2] + d1[2]);
                float e3 = __expf(d0[3] + d1[3]);
                sm0 += e0 + e1; sm1 += e2 + e3;
                int col = nt2 * 8 + 2 * c;
                float2 v01 = {e0, e1};
                float2 v23 = {e2, e3};
                *(float2*)&ew[g * ESP + col] = v01;
                *(float2*)&ew[(g + 8) * ESP + col] = v23;
            }
            __syncwarp();
#pragma unroll
            for (int kg = 0; kg < 2; kg++) {
                uint32_t a[4];
                a[0] = __float_as_uint(ew[g * ESP + kg * 8 + c]);
                a[1] = __float_as_uint(ew[(g + 8) * ESP + kg * 8 + c]);
                a[2] = __float_as_uint(ew[g * ESP + kg * 8 + c + 4]);
                a[3] = __float_as_uint(ew[(g + 8) * ESP + kg * 8 + c + 4]);
                int mr = sb * 16 + kg * 8;
#pragma unroll
                for (int nt = 0; nt < 8; nt++) {
                    int w0 = nt * 8;
                    uint32_t bh0, bl0, bh1, bl1;
                    msp(ms[(mr + c) * MSP + w0 + g], bh0, bl0);
                    msp(ms[(mr + c + 4) * MSP + w0 + g], bh1, bl1);
                    mma8(acc[nt], a, bh0, bh1);
                    mma8(acc[nt], a, bl0, bl1);
                }
            }
            __syncwarp();
        }
        __syncthreads();
    }

    sm0 += __shfl_xor_sync(0xffffffffu, sm0, 1);
    sm0 += __shfl_xor_sync(0xffffffffu, sm0, 2);
    sm1 += __shfl_xor_sync(0xffffffffu, sm1, 1);
    sm1 += __shfl_xor_sync(0xffffffffu, sm1, 2);
    float inv0 = 1.f / sm0, inv1 = 1.f / sm1;
    float* ob = out + ((size_t)b * 512 + s0 * 4) * WD;
#pragma unroll
    for (int nt = 0; nt < 8; nt++) {
        int col = nt * 8 + 2 * c;
        float2 v01 = {acc[nt][0] * inv0, acc[nt][1] * inv0};
        float2 v23 = {acc[nt][2] * inv1, acc[nt][3] * inv1};
        *(float2*)&ob[(size_t)(wrow + g) * WD + col] = v01;
        *(float2*)&ob[(size_t)(wrow + g + 8) * WD + col] = v23;
    }

    // ---- fused final_state (b == B-1, 4 blocks): recompute scores, normalize ----
    if (b == BB - 1) {
        float* fs = out + (size_t)BB * SS * RR * WD;
        for (int ch = 0; ch < 4; ch++) {
            for (int i = tid; i < 128 * 16; i += 256) {
                int m = i >> 4, w4 = (i & 15) * 4;
                *(float4*)&ms[m * MSP + w4] = *(const float4*)&M[(size_t)(ch * 128 + m) * WD + w4];
            }
            __syncthreads();
            for (int sb = 0; sb < 8; sb++) {
#pragma unroll
                for (int nt2 = 0; nt2 < 2; nt2++) {
                    int mc = sb * 16 + nt2 * 8;
                    float d[4] = {0.f, 0.f, 0.f, 0.f};
#pragma unroll
                    for (int k = 0; k < 8; k++) {
                        uint32_t bh0, bl0, bh1, bl1;
                        msp(ms[(mc + g) * MSP + k * 8 + c], bh0, bl0);
                        msp(ms[(mc + g) * MSP + k * 8 + c + 4], bh1, bl1);
                        mma8(d, ah[k], bh0, bh1);
                        mma8(d, ah[k], bl0, bl1);
                        mma8(d, al[k], bh0, bh1);
                    }
                    int col = ch * 128 + mc + 2 * c;
                    float2 v01 = {__expf(d[0]) * inv0, __expf(d[1]) * inv0};
                    float2 v23 = {__expf(d[2]) * inv1, __expf(d[3]) * inv1};
                    *(float2*)&fs[(size_t)(s0 * 4 + wrow + g) * MSZ + col] = v01;
                    *(float2*)&fs[(size_t)(s0 * 4 + wrow + g + 8) * MSZ + col] = v23;
                }
            }
            __syncthreads();
        }
    }
}

extern "C" void kernel_launch(void* const* d_in, const int* in_sizes, int n_in,
                              void* d_out, int out_size) {
    const float* x = (const float*)d_in[0];
    const int* uid = (const int*)d_in[1];
    const float* tab = (const float*)d_in[2];
    const float* Wp = (const float*)d_in[3];
    const float* bp = (const float*)d_in[4];
    const float* Wq = (const float*)d_in[5];
    const float* memp = (const float*)d_in[6];
    float* out = (float*)d_out;

    k_uid<<<1, 256>>>(uid);
    k_pe<<<BB, 128>>>(tab, Wp, bp);
    dim3 g2(4, 2, BB);
    k_qgemm<<<g2, 256>>>(x, Wq);

    const int smem_bytes = (2 * 128 * MSP + 8 * 16 * ESP) * 4;
    cudaFuncSetAttribute(k_attn, cudaFuncAttributeMaxDynamicSharedMemorySize, smem_bytes);
    dim3 g3(4, BB);
    k_attn<<<g3, 256, smem_bytes>>>(memp, out);
}

// round 13
// speedup vs baseline: 1.4924x; 1.4924x over previous
#include <cuda_runtime.h>
#include <cstdint>

#define NUSERS 100000
#define E 64
#define P 128
#define NSHARD 16
#define MSZ 512
#define WD 64
#define RR 4
#define INSZ 256
#define BB 256
#define SS 128
#define IND 384
#define QO 256

#define MSP 68
#define ESP 20

__device__ float g_pe[BB * P];
__device__ float g_q[(size_t)BB * SS * QO];
__device__ int g_uid[BB];

__global__ void k_uid(const int* __restrict__ u) {
    int s = 2;
#pragma unroll
    for (int i = 0; i < 8; i++)
        if (u[2 * i + 1] != 0) s = 1;
    int b = blockIdx.x * blockDim.x + threadIdx.x;
    if (b < BB) g_uid[b] = u[b * s];
}

__device__ __forceinline__ void msp(float x, uint32_t& h, uint32_t& l) {
    h = __float_as_uint(x) & 0xFFFFE000u;
    l = __float_as_uint(x - __uint_as_float(h));
}
__device__ __forceinline__ void mma8(float d[4], const uint32_t a[4], uint32_t b0, uint32_t b1) {
    asm volatile(
        "mma.sync.aligned.m16n8k8.row.col.f32.tf32.tf32.f32 "
        "{%0,%1,%2,%3}, {%4,%5,%6,%7}, {%8,%9}, {%0,%1,%2,%3};"
        : "+f"(d[0]), "+f"(d[1]), "+f"(d[2]), "+f"(d[3])
        : "r"(a[0]), "r"(a[1]), "r"(a[2]), "r"(a[3]), "r"(b0), "r"(b1));
}
__device__ __forceinline__ uint32_t smem_u32(const void* p) {
    uint32_t a;
    asm("{ .reg .u64 t; cvta.to.shared.u64 t, %1; cvt.u32.u64 %0, t; }" : "=r"(a) : "l"(p));
    return a;
}
__device__ __forceinline__ void cpa16(uint32_t s, const void* g) {
    asm volatile("cp.async.ca.shared.global [%0], [%1], 16;" :: "r"(s), "l"(g));
}
__device__ __forceinline__ void cpcommit() { asm volatile("cp.async.commit_group;"); }
__device__ __forceinline__ void cpwait1() { asm volatile("cp.async.wait_group 1;"); }
__device__ __forceinline__ void cpwait0() { asm volatile("cp.async.wait_group 0;"); }

__global__ void k_pe(const float* __restrict__ tab, const float* __restrict__ Wp,
                     const float* __restrict__ bp) {
    __shared__ float ue[E];
    int b = blockIdx.x;
    int t = threadIdx.x;
    int uid = g_uid[b];
    if (t < E) ue[t] = tab[(size_t)uid * E + t];
    __syncthreads();
    float acc = bp[t];
#pragma unroll
    for (int e = 0; e < E; e++) acc += ue[e] * Wp[e * P + t];
    g_pe[b * P + t] = acc;
}

// --- q = concat(x, pe) @ Wq[sid]; cp.async double-buffered, 8 acc chains ---
__global__ __launch_bounds__(256) void k_qgemm(const float* __restrict__ x,
                                               const float* __restrict__ Wq) {
    __shared__ float As[2][64][36];
    __shared__ float Bs[2][32][68];
    int b = blockIdx.z;
    int n0 = blockIdx.x * 64, m0 = blockIdx.y * 64;
    int sid = ((unsigned)g_uid[b]) % NSHARD;
    const float* Wg = Wq + (size_t)sid * IND * QO;
    int tid = threadIdx.x;
    int lane = tid & 31, warp = tid >> 5;
    int g = lane >> 2, c = lane & 3;
    int wm = warp & 3, wn = warp >> 2;
    const float* xb = x + ((size_t)b * SS + m0) * INSZ;
    const float* pe = g_pe + b * P;
    uint32_t asb = smem_u32(&As[0][0][0]);
    uint32_t bsb = smem_u32(&Bs[0][0][0]);

    float d[2][4][4];
#pragma unroll
    for (int p = 0; p < 2; p++)
#pragma unroll
        for (int i = 0; i < 4; i++)
#pragma unroll
            for (int j = 0; j < 4; j++) d[p][i][j] = 0.f;

#define LOADTILE(t, buf)                                                                  \
    do {                                                                                  \
        int k0_ = (t) * 32;                                                               \
        for (int i = tid; i < 512; i += 256) {                                            \
            int row = i >> 3, k4 = (i & 7) * 4;                                           \
            const float* src = (k0_ < INSZ) ? &xb[row * INSZ + k0_ + k4]                  \
                                            : &pe[k0_ - INSZ + k4];                       \
            cpa16(asb + ((buf) * 64 * 36 + row * 36 + k4) * 4, src);                      \
        }                                                                                 \
        for (int i = tid; i < 512; i += 256) {                                            \
            int kk = i >> 4, n4 = (i & 15) * 4;                                           \
            cpa16(bsb + ((buf) * 32 * 68 + kk * 68 + n4) * 4,                             \
                  &Wg[(size_t)(k0_ + kk) * QO + n0 + n4]);                                \
        }                                                                                 \
    } while (0)

    LOADTILE(0, 0);
    cpcommit();

    for (int t = 0; t < 12; t++) {
        int buf = t & 1;
        if (t < 11) {
            LOADTILE(t + 1, buf ^ 1);
            cpcommit();
            cpwait1();
        } else {
            cpwait0();
        }
        __syncthreads();
#pragma unroll
        for (int ks = 0; ks < 4; ks++) {
            int par = ks & 1;
            uint32_t ah[4], al[4];
            msp(As[buf][wm * 16 + g][ks * 8 + c], ah[0], al[0]);
            msp(As[buf][wm * 16 + g + 8][ks * 8 + c], ah[1], al[1]);
            msp(As[buf][wm * 16 + g][ks * 8 + c + 4], ah[2], al[2]);
            msp(As[buf][wm * 16 + g + 8][ks * 8 + c + 4], ah[3], al[3]);
#pragma unroll
            for (int nt = 0; nt < 4; nt++) {
                int nn = wn * 32 + nt * 8;
                uint32_t bh0, bl0, bh1, bl1;
                msp(Bs[buf][ks * 8 + c][nn + g], bh0, bl0);
                msp(Bs[buf][ks * 8 + c + 4][nn + g], bh1, bl1);
                mma8(d[par][nt], ah, bh0, bh1);
                mma8(d[par][nt], ah, bl0, bl1);
                mma8(d[par][nt], al, bh0, bh1);
            }
        }
        __syncthreads();
    }
    float* qb = g_q + ((size_t)b * SS + m0) * QO + n0;
#pragma unroll
    for (int nt = 0; nt < 4; nt++) {
        int nn = wn * 32 + nt * 8 + 2 * c;
        float2 v01 = {d[0][nt][0] + d[1][nt][0], d[0][nt][1] + d[1][nt][1]};
        float2 v23 = {d[0][nt][2] + d[1][nt][2], d[0][nt][3] + d[1][nt][3]};
        *(float2*)&qb[(size_t)(wm * 16 + g) * QO + nn] = v01;
        *(float2*)&qb[(size_t)(wm * 16 + g + 8) * QO + nn] = v23;
    }
}

// ---- flash attention, warp-shared max (rescale fires ~ln(32) times, bit-exact skip) ----
__global__ __launch_bounds__(256, 2) void k_attn(const float* __restrict__ mem,
                                                 float* __restrict__ out) {
    extern __shared__ float sm[];
    float* qs = sm;
    float* ms = qs + 128 * MSP;
    float* es = ms + 128 * MSP;

    int tid = threadIdx.x;
    int lane = tid & 31, warp = tid >> 5;
    int g = lane >> 2, c = lane & 3;
    int b = blockIdx.y;
    int s0 = blockIdx.x * 32;
    int sid = ((unsigned)g_uid[b]) % NSHARD;
    const float* M = mem + (size_t)sid * MSZ * WD;
    float* ew = es + warp * (16 * ESP);
    int wrow = warp * 16;

    const float* qsrc = g_q + ((size_t)b * SS + s0) * QO;
    for (int i = tid; i < 128 * 16; i += 256) {
        int row = i >> 4, w4 = (i & 15) * 4;
        float4 v = *(const float4*)&qsrc[(size_t)(row >> 2) * QO + (row & 3) * WD + w4];
        *(float4*)&qs[row * MSP + w4] = v;
    }

    uint32_t ah[8][4], al[8][4];
    float acc[8][4];
#pragma unroll
    for (int nt = 0; nt < 8; nt++)
#pragma unroll
        for (int j = 0; j < 4; j++) acc[nt][j] = 0.f;
    float mx = -1e30f, sm0 = 0.f, sm1 = 0.f;

    for (int ch = 0; ch < 4; ch++) {
        for (int i = tid; i < 128 * 16; i += 256) {
            int m = i >> 4, w4 = (i & 15) * 4;
            *(float4*)&ms[m * MSP + w4] = *(const float4*)&M[(size_t)(ch * 128 + m) * WD + w4];
        }
        __syncthreads();
        if (ch == 0) {
#pragma unroll
            for (int k = 0; k < 8; k++) {
                msp(qs[(wrow + g) * MSP + k * 8 + c], ah[k][0], al[k][0]);
                msp(qs[(wrow + g + 8) * MSP + k * 8 + c], ah[k][1], al[k][1]);
                msp(qs[(wrow + g) * MSP + k * 8 + c + 4], ah[k][2], al[k][2]);
                msp(qs[(wrow + g + 8) * MSP + k * 8 + c + 4], ah[k][3], al[k][3]);
            }
        }
        for (int sb = 0; sb < 8; sb++) {
            float e[2][4];
#pragma unroll
            for (int nt2 = 0; nt2 < 2; nt2++) {
                int mc = sb * 16 + nt2 * 8;
                float d0[4] = {0.f, 0.f, 0.f, 0.f};
                float d1[4] = {0.f, 0.f, 0.f, 0.f};
#pragma unroll
                for (int k = 0; k < 8; k += 2) {
                    uint32_t bh0, bl0, bh1, bl1;
                    msp(ms[(mc + g) * MSP + k * 8 + c], bh0, bl0);
                    msp(ms[(mc + g) * MSP + k * 8 + c + 4], bh1, bl1);
                    mma8(d0, ah[k], bh0, bh1);
                    mma8(d0, ah[k], bl0, bl1);
                    mma8(d0, al[k], bh0, bh1);
                    uint32_t ch0, cl0, ch1, cl1;
                    msp(ms[(mc + g) * MSP + (k + 1) * 8 + c], ch0, cl0);
                    msp(ms[(mc + g) * MSP + (k + 1) * 8 + c + 4], ch1, cl1);
                    mma8(d1, ah[k + 1], ch0, ch1);
                    mma8(d1, ah[k + 1], cl0, cl1);
                    mma8(d1, al[k + 1], ch0, ch1);
                }
#pragma unroll
                for (int j = 0; j < 4; j++) e[nt2][j] = d0[j] + d1[j];
            }
            // warp-shared max over all 16 rows x 16 cols of this sub-block
            float m = fmaxf(fmaxf(fmaxf(e[0][0], e[0][1]), fmaxf(e[0][2], e[0][3])),
                            fmaxf(fmaxf(e[1][0], e[1][1]), fmaxf(e[1][2], e[1][3])));
#pragma unroll
            for (int o = 16; o > 0; o >>= 1) m = fmaxf(m, __shfl_xor_sync(0xffffffffu, m, o));
            if (m > mx) {  // warp-uniform, rare after first chunk
                float sc = __expf(mx - m);
                sm0 *= sc; sm1 *= sc;
#pragma unroll
                for (int nt = 0; nt < 8; nt++) {
                    acc[nt][0] *= sc; acc[nt][1] *= sc;
                    acc[nt][2] *= sc; acc[nt][3] *= sc;
                }
                mx = m;
            }
#pragma unroll
            for (int nt2 = 0; nt2 < 2; nt2++) {
                float e0 = __expf(e[nt2][0] - mx);
                float e1 = __expf(e[nt2][1] - mx);
                float e2 = __expf(e[nt2][2] - mx);
                float e3 = __expf(e[nt2][3] - mx);
                sm0 += e0 + e1; sm1 += e2 + e3;
                int col = nt2 * 8 + 2 * c;
                float2 v01 = {e0, e1};
                float2 v23 = {e2, e3};
                *(float2*)&ew[g * ESP + col] = v01;
                *(float2*)&ew[(g + 8) * ESP + col] = v23;
            }
            __syncwarp();
#pragma unroll
            for (int kg = 0; kg < 2; kg++) {
                uint32_t a[4];
                a[0] = __float_as_uint(ew[g * ESP + kg * 8 + c]);
                a[1] = __float_as_uint(ew[(g + 8) * ESP + kg * 8 + c]);
                a[2] = __float_as_uint(ew[g * ESP + kg * 8 + c + 4]);
                a[3] = __float_as_uint(ew[(g + 8) * ESP + kg * 8 + c + 4]);
                int mr = sb * 16 + kg * 8;
#pragma unroll
                for (int nt = 0; nt < 8; nt++) {
                    int w0 = nt * 8;
                    uint32_t bh0, bl0, bh1, bl1;
                    msp(ms[(mr + c) * MSP + w0 + g], bh0, bl0);
                    msp(ms[(mr + c + 4) * MSP + w0 + g], bh1, bl1);
                    mma8(acc[nt], a, bh0, bh1);
                    mma8(acc[nt], a, bl0, bl1);
                }
            }
            __syncwarp();
        }
        __syncthreads();
    }

    sm0 += __shfl_xor_sync(0xffffffffu, sm0, 1);
    sm0 += __shfl_xor_sync(0xffffffffu, sm0, 2);
    sm1 += __shfl_xor_sync(0xffffffffu, sm1, 1);
    sm1 += __shfl_xor_sync(0xffffffffu, sm1, 2);
    float inv0 = 1.f / sm0, inv1 = 1.f / sm1;
    float* ob = out + ((size_t)b * 512 + s0 * 4) * WD;
#pragma unroll
    for (int nt = 0; nt < 8; nt++) {
        int col = nt * 8 + 2 * c;
        float2 v01 = {acc[nt][0] * inv0, acc[nt][1] * inv0};
        float2 v23 = {acc[nt][2] * inv1, acc[nt][3] * inv1};
        *(float2*)&ob[(size_t)(wrow + g) * WD + col] = v01;
        *(float2*)&ob[(size_t)(wrow + g + 8) * WD + col] = v23;
    }

    // ---- fused final_state (b == B-1, 4 blocks): recompute scores, normalize ----
    if (b == BB - 1) {
        float* fs = out + (size_t)BB * SS * RR * WD;
        for (int ch = 0; ch < 4; ch++) {
            for (int i = tid; i < 128 * 16; i += 256) {
                int m = i >> 4, w4 = (i & 15) * 4;
                *(float4*)&ms[m * MSP + w4] = *(const float4*)&M[(size_t)(ch * 128 + m) * WD + w4];
            }
            __syncthreads();
            for (int sb = 0; sb < 8; sb++) {
#pragma unroll
                for (int nt2 = 0; nt2 < 2; nt2++) {
                    int mc = sb * 16 + nt2 * 8;
                    float d[4] = {0.f, 0.f, 0.f, 0.f};
#pragma unroll
                    for (int k = 0; k < 8; k++) {
                        uint32_t bh0, bl0, bh1, bl1;
                        msp(ms[(mc + g) * MSP + k * 8 + c], bh0, bl0);
                        msp(ms[(mc + g) * MSP + k * 8 + c + 4], bh1, bl1);
                        mma8(d, ah[k], bh0, bh1);
                        mma8(d, ah[k], bl0, bl1);
                        mma8(d, al[k], bh0, bh1);
                    }
                    int col = ch * 128 + mc + 2 * c;
                    float2 v01 = {__expf(d[0] - mx) * inv0, __expf(d[1] - mx) * inv0};
                    float2 v23 = {__expf(d[2] - mx) * inv1, __expf(d[3] - mx) * inv1};
                    *(float2*)&fs[(size_t)(s0 * 4 + wrow + g) * MSZ + col] = v01;
                    *(float2*)&fs[(size_t)(s0 * 4 + wrow + g + 8) * MSZ + col] = v23;
                }
            }
            __syncthreads();
        }
    }
}

extern "C" void kernel_launch(void* const* d_in, const int* in_sizes, int n_in,
                              void* d_out, int out_size) {
    const float* x = (const float*)d_in[0];
    const int* uid = (const int*)d_in[1];
    const float* tab = (const float*)d_in[2];
    const float* Wp = (const float*)d_in[3];
    const float* bp = (const float*)d_in[4];
    const float* Wq = (const float*)d_in[5];
    const float* memp = (const float*)d_in[6];
    float* out = (float*)d_out;

    k_uid<<<1, 256>>>(uid);
    k_pe<<<BB, 128>>>(tab, Wp, bp);
    dim3 g2(4, 2, BB);
    k_qgemm<<<g2, 256>>>(x, Wq);

    const int smem_bytes = (2 * 128 * MSP + 8 * 16 * ESP) * 4;
    cudaFuncSetAttribute(k_attn, cudaFuncAttributeMaxDynamicSharedMemorySize, smem_bytes);
    dim3 g3(4, BB);
    k_attn<<<g3, 256, smem_bytes>>>(memp, out);
}

// round 14
// speedup vs baseline: 1.5096x; 1.0115x over previous
#include <cuda_runtime.h>
#include <cstdint>

#define NUSERS 100000
#define E 64
#define P 128
#define NSHARD 16
#define MSZ 512
#define WD 64
#define RR 4
#define INSZ 256
#define BB 256
#define SS 128
#define IND 384
#define QO 256

#define MSP 68
#define ESP 20

__device__ float g_pe[BB * P];
__device__ float g_q[(size_t)BB * SS * QO];
__device__ int g_uid[BB];

__global__ void k_uid(const int* __restrict__ u) {
    int s = 2;
#pragma unroll
    for (int i = 0; i < 8; i++)
        if (u[2 * i + 1] != 0) s = 1;
    int b = blockIdx.x * blockDim.x + threadIdx.x;
    if (b < BB) g_uid[b] = u[b * s];
}

__device__ __forceinline__ void msp(float x, uint32_t& h, uint32_t& l) {
    h = __float_as_uint(x) & 0xFFFFE000u;
    l = __float_as_uint(x - __uint_as_float(h));
}
__device__ __forceinline__ void mma8(float d[4], const uint32_t a[4], uint32_t b0, uint32_t b1) {
    asm volatile(
        "mma.sync.aligned.m16n8k8.row.col.f32.tf32.tf32.f32 "
        "{%0,%1,%2,%3}, {%4,%5,%6,%7}, {%8,%9}, {%0,%1,%2,%3};"
        : "+f"(d[0]), "+f"(d[1]), "+f"(d[2]), "+f"(d[3])
        : "r"(a[0]), "r"(a[1]), "r"(a[2]), "r"(a[3]), "r"(b0), "r"(b1));
}
__device__ __forceinline__ uint32_t smem_u32(const void* p) {
    uint32_t a;
    asm("{ .reg .u64 t; cvta.to.shared.u64 t, %1; cvt.u32.u64 %0, t; }" : "=r"(a) : "l"(p));
    return a;
}
__device__ __forceinline__ void cpa16(uint32_t s, const void* g) {
    asm volatile("cp.async.ca.shared.global [%0], [%1], 16;" :: "r"(s), "l"(g));
}
__device__ __forceinline__ void cpcommit() { asm volatile("cp.async.commit_group;"); }
__device__ __forceinline__ void cpwait1() { asm volatile("cp.async.wait_group 1;"); }
__device__ __forceinline__ void cpwait0() { asm volatile("cp.async.wait_group 0;"); }

__global__ void k_pe(const float* __restrict__ tab, const float* __restrict__ Wp,
                     const float* __restrict__ bp) {
    __shared__ float ue[E];
    int b = blockIdx.x;
    int t = threadIdx.x;
    int uid = g_uid[b];
    if (t < E) ue[t] = tab[(size_t)uid * E + t];
    __syncthreads();
    float acc = bp[t];
#pragma unroll
    for (int e = 0; e < E; e++) acc += ue[e] * Wp[e * P + t];
    g_pe[b * P + t] = acc;
}

// --- q = concat(x, pe) @ Wq[sid]; 64x128 block, warp tile 16x64, dyn smem ---
__global__ __launch_bounds__(256) void k_qgemm(const float* __restrict__ x,
                                               const float* __restrict__ Wq) {
    extern __shared__ float qsm[];
    float* As = qsm;                 // [2][64][36]
    float* Bs = qsm + 2 * 64 * 36;   // [2][32][132]
    int b = blockIdx.z;
    int n0 = blockIdx.x * 128, m0 = blockIdx.y * 64;
    int sid = ((unsigned)g_uid[b]) % NSHARD;
    const float* Wg = Wq + (size_t)sid * IND * QO;
    int tid = threadIdx.x;
    int lane = tid & 31, warp = tid >> 5;
    int g = lane >> 2, c = lane & 3;
    int wm = warp & 3, wn = warp >> 2;  // 4 m-tiles x 2 n-halves
    const float* xb = x + ((size_t)b * SS + m0) * INSZ;
    const float* pe = g_pe + b * P;
    uint32_t asb = smem_u32(As);
    uint32_t bsb = smem_u32(Bs);

    float d[8][4];
#pragma unroll
    for (int i = 0; i < 8; i++)
#pragma unroll
        for (int j = 0; j < 4; j++) d[i][j] = 0.f;

#define LOADTILE(t, buf)                                                                  \
    do {                                                                                  \
        int k0_ = (t) * 32;                                                               \
        for (int i = tid; i < 512; i += 256) {                                            \
            int row = i >> 3, k4 = (i & 7) * 4;                                           \
            const float* src = (k0_ < INSZ) ? &xb[row * INSZ + k0_ + k4]                  \
                                            : &pe[k0_ - INSZ + k4];                       \
            cpa16(asb + ((buf) * 64 * 36 + row * 36 + k4) * 4, src);                      \
        }                                                                                 \
        for (int i = tid; i < 1024; i += 256) {                                           \
            int kk = i >> 5, n4 = (i & 31) * 4;                                           \
            cpa16(bsb + ((buf) * 32 * 132 + kk * 132 + n4) * 4,                           \
                  &Wg[(size_t)(k0_ + kk) * QO + n0 + n4]);                                \
        }                                                                                 \
    } while (0)

    LOADTILE(0, 0);
    cpcommit();

    for (int t = 0; t < 12; t++) {
        int buf = t & 1;
        if (t < 11) {
            LOADTILE(t + 1, buf ^ 1);
            cpcommit();
            cpwait1();
        } else {
            cpwait0();
        }
        __syncthreads();
#pragma unroll
        for (int ks = 0; ks < 4; ks++) {
            uint32_t ah[4], al[4];
            msp(As[buf * 2304 + (wm * 16 + g) * 36 + ks * 8 + c], ah[0], al[0]);
            msp(As[buf * 2304 + (wm * 16 + g + 8) * 36 + ks * 8 + c], ah[1], al[1]);
            msp(As[buf * 2304 + (wm * 16 + g) * 36 + ks * 8 + c + 4], ah[2], al[2]);
            msp(As[buf * 2304 + (wm * 16 + g + 8) * 36 + ks * 8 + c + 4], ah[3], al[3]);
#pragma unroll
            for (int nt = 0; nt < 8; nt++) {
                int nn = wn * 64 + nt * 8;
                uint32_t bh0, bl0, bh1, bl1;
                msp(Bs[buf * 4224 + (ks * 8 + c) * 132 + nn + g], bh0, bl0);
                msp(Bs[buf * 4224 + (ks * 8 + c + 4) * 132 + nn + g], bh1, bl1);
                mma8(d[nt], ah, bh0, bh1);
                mma8(d[nt], ah, bl0, bl1);
                mma8(d[nt], al, bh0, bh1);
            }
        }
        __syncthreads();
    }
    float* qb = g_q + ((size_t)b * SS + m0) * QO + n0;
#pragma unroll
    for (int nt = 0; nt < 8; nt++) {
        int nn = wn * 64 + nt * 8 + 2 * c;
        float2 v01 = {d[nt][0], d[nt][1]};
        float2 v23 = {d[nt][2], d[nt][3]};
        *(float2*)&qb[(size_t)(wm * 16 + g) * QO + nn] = v01;
        *(float2*)&qb[(size_t)(wm * 16 + g + 8) * QO + nn] = v23;
    }
}

// ---- flash attention, phase-2 software-pipelined into phase-1 (double-buffered ew) ----
__global__ __launch_bounds__(256, 2) void k_attn(const float* __restrict__ mem,
                                                 float* __restrict__ out) {
    extern __shared__ float sm[];
    float* qs = sm;
    float* ms = qs + 128 * MSP;
    float* es = ms + 128 * MSP;  // 8 warps x 2 bufs x [16][ESP]

    int tid = threadIdx.x;
    int lane = tid & 31, warp = tid >> 5;
    int g = lane >> 2, c = lane & 3;
    int b = blockIdx.y;
    int s0 = blockIdx.x * 32;
    int sid = ((unsigned)g_uid[b]) % NSHARD;
    const float* M = mem + (size_t)sid * MSZ * WD;
    float* ew = es + warp * (2 * 16 * ESP);
    int wrow = warp * 16;

    const float* qsrc = g_q + ((size_t)b * SS + s0) * QO;
    for (int i = tid; i < 128 * 16; i += 256) {
        int row = i >> 4, w4 = (i & 15) * 4;
        float4 v = *(const float4*)&qsrc[(size_t)(row >> 2) * QO + (row & 3) * WD + w4];
        *(float4*)&qs[row * MSP + w4] = v;
    }

    uint32_t ah[8][4], al[8][4];
    float acc[8][4];
#pragma unroll
    for (int nt = 0; nt < 8; nt++)
#pragma unroll
        for (int j = 0; j < 4; j++) acc[nt][j] = 0.f;
    float mx = -1e30f, sm0 = 0.f, sm1 = 0.f;

// phase-2 block for one kg of the PREVIOUS sub-block (reads ewp, mem rows prm+kg*8..)
#define P2KG(ewp, prm, kg)                                                                \
    do {                                                                                  \
        uint32_t a[4];                                                                    \
        a[0] = __float_as_uint((ewp)[g * ESP + (kg) * 8 + c]);                            \
        a[1] = __float_as_uint((ewp)[(g + 8) * ESP + (kg) * 8 + c]);                      \
        a[2] = __float_as_uint((ewp)[g * ESP + (kg) * 8 + c + 4]);                        \
        a[3] = __float_as_uint((ewp)[(g + 8) * ESP + (kg) * 8 + c + 4]);                  \
        int mr = (prm) + (kg) * 8;                                                        \
        _Pragma("unroll") for (int nt = 0; nt < 8; nt++) {                                \
            int w0 = nt * 8;                                                              \
            uint32_t bh0, bl0, bh1, bl1;                                                  \
            msp(ms[(mr + c) * MSP + w0 + g], bh0, bl0);                                   \
            msp(ms[(mr + c + 4) * MSP + w0 + g], bh1, bl1);                               \
            mma8(acc[nt], a, bh0, bh1);                                                   \
            mma8(acc[nt], a, bl0, bl1);                                                   \
        }                                                                                 \
    } while (0)

    for (int ch = 0; ch < 4; ch++) {
        for (int i = tid; i < 128 * 16; i += 256) {
            int m = i >> 4, w4 = (i & 15) * 4;
            *(float4*)&ms[m * MSP + w4] = *(const float4*)&M[(size_t)(ch * 128 + m) * WD + w4];
        }
        __syncthreads();
        if (ch == 0) {
#pragma unroll
            for (int k = 0; k < 8; k++) {
                msp(qs[(wrow + g) * MSP + k * 8 + c], ah[k][0], al[k][0]);
                msp(qs[(wrow + g + 8) * MSP + k * 8 + c], ah[k][1], al[k][1]);
                msp(qs[(wrow + g) * MSP + k * 8 + c + 4], ah[k][2], al[k][2]);
                msp(qs[(wrow + g + 8) * MSP + k * 8 + c + 4], ah[k][3], al[k][3]);
            }
        }
        for (int sb = 0; sb < 8; sb++) {
            float* ewc = ew + (sb & 1) * (16 * ESP);
            float* ewp = ew + ((sb & 1) ^ 1) * (16 * ESP);
            int prm = (sb - 1) * 16;
            float e[2][4];
            // phase1 nt2=0
            {
                int mc = sb * 16;
                float d0[4] = {0.f, 0.f, 0.f, 0.f};
                float d1[4] = {0.f, 0.f, 0.f, 0.f};
#pragma unroll
                for (int k = 0; k < 8; k += 2) {
                    uint32_t bh0, bl0, bh1, bl1;
                    msp(ms[(mc + g) * MSP + k * 8 + c], bh0, bl0);
                    msp(ms[(mc + g) * MSP + k * 8 + c + 4], bh1, bl1);
                    mma8(d0, ah[k], bh0, bh1);
                    mma8(d0, ah[k], bl0, bl1);
                    mma8(d0, al[k], bh0, bh1);
                    uint32_t ch0, cl0, ch1, cl1;
                    msp(ms[(mc + g) * MSP + (k + 1) * 8 + c], ch0, cl0);
                    msp(ms[(mc + g) * MSP + (k + 1) * 8 + c + 4], ch1, cl1);
                    mma8(d1, ah[k + 1], ch0, ch1);
                    mma8(d1, ah[k + 1], cl0, cl1);
                    mma8(d1, al[k + 1], ch0, ch1);
                }
#pragma unroll
                for (int j = 0; j < 4; j++) e[0][j] = d0[j] + d1[j];
            }
            // phase2 prev, kg=0 (independent chains keep tensor pipe fed)
            if (sb > 0) P2KG(ewp, prm, 0);
            // phase1 nt2=1
            {
                int mc = sb * 16 + 8;
                float d0[4] = {0.f, 0.f, 0.f, 0.f};
                float d1[4] = {0.f, 0.f, 0.f, 0.f};
#pragma unroll
                for (int k = 0; k < 8; k += 2) {
                    uint32_t bh0, bl0, bh1, bl1;
                    msp(ms[(mc + g) * MSP + k * 8 + c], bh0, bl0);
                    msp(ms[(mc + g) * MSP + k * 8 + c + 4], bh1, bl1);
                    mma8(d0, ah[k], bh0, bh1);
                    mma8(d0, ah[k], bl0, bl1);
                    mma8(d0, al[k], bh0, bh1);
                    uint32_t ch0, cl0, ch1, cl1;
                    msp(ms[(mc + g) * MSP + (k + 1) * 8 + c], ch0, cl0);
                    msp(ms[(mc + g) * MSP + (k + 1) * 8 + c + 4], ch1, cl1);
                    mma8(d1, ah[k + 1], ch0, ch1);
                    mma8(d1, ah[k + 1], cl0, cl1);
                    mma8(d1, al[k + 1], ch0, ch1);
                }
#pragma unroll
                for (int j = 0; j < 4; j++) e[1][j] = d0[j] + d1[j];
            }
            // phase2 prev, kg=1
            if (sb > 0) P2KG(ewp, prm, 1);
            // softmax bookkeeping (warp-shared max, rare bit-exact rescale)
            float m = fmaxf(fmaxf(fmaxf(e[0][0], e[0][1]), fmaxf(e[0][2], e[0][3])),
                            fmaxf(fmaxf(e[1][0], e[1][1]), fmaxf(e[1][2], e[1][3])));
#pragma unroll
            for (int o = 16; o > 0; o >>= 1) m = fmaxf(m, __shfl_xor_sync(0xffffffffu, m, o));
            if (m > mx) {
                float sc = __expf(mx - m);
                sm0 *= sc; sm1 *= sc;
#pragma unroll
                for (int nt = 0; nt < 8; nt++) {
                    acc[nt][0] *= sc; acc[nt][1] *= sc;
                    acc[nt][2] *= sc; acc[nt][3] *= sc;
                }
                mx = m;
            }
#pragma unroll
            for (int nt2 = 0; nt2 < 2; nt2++) {
                float e0 = __expf(e[nt2][0] - mx);
                float e1 = __expf(e[nt2][1] - mx);
                float e2 = __expf(e[nt2][2] - mx);
                float e3 = __expf(e[nt2][3] - mx);
                sm0 += e0 + e1; sm1 += e2 + e3;
                int col = nt2 * 8 + 2 * c;
                float2 v01 = {e0, e1};
                float2 v23 = {e2, e3};
                *(float2*)&ewc[g * ESP + col] = v01;
                *(float2*)&ewc[(g + 8) * ESP + col] = v23;
            }
            __syncwarp();
        }
        // drain: phase2 for sb=7 before ms is restaged
        {
            float* ewp = ew + (16 * ESP);  // sb=7 stored in buf 1
            P2KG(ewp, 7 * 16, 0);
            P2KG(ewp, 7 * 16, 1);
        }
        __syncthreads();
    }

    sm0 += __shfl_xor_sync(0xffffffffu, sm0, 1);
    sm0 += __shfl_xor_sync(0xffffffffu, sm0, 2);
    sm1 += __shfl_xor_sync(0xffffffffu, sm1, 1);
    sm1 += __shfl_xor_sync(0xffffffffu, sm1, 2);
    float inv0 = 1.f / sm0, inv1 = 1.f / sm1;
    float* ob = out + ((size_t)b * 512 + s0 * 4) * WD;
#pragma unroll
    for (int nt = 0; nt < 8; nt++) {
        int col = nt * 8 + 2 * c;
        float2 v01 = {acc[nt][0] * inv0, acc[nt][1] * inv0};
        float2 v23 = {acc[nt][2] * inv1, acc[nt][3] * inv1};
        *(float2*)&ob[(size_t)(wrow + g) * WD + col] = v01;
        *(float2*)&ob[(size_t)(wrow + g + 8) * WD + col] = v23;
    }

    // ---- fused final_state (b == B-1, 4 blocks): recompute scores, normalize ----
    if (b == BB - 1) {
        float* fs = out + (size_t)BB * SS * RR * WD;
        for (int ch = 0; ch < 4; ch++) {
            for (int i = tid; i < 128 * 16; i += 256) {
                int m = i >> 4, w4 = (i & 15) * 4;
                *(float4*)&ms[m * MSP + w4] = *(const float4*)&M[(size_t)(ch * 128 + m) * WD + w4];
            }
            __syncthreads();
            for (int sb = 0; sb < 8; sb++) {
#pragma unroll
                for (int nt2 = 0; nt2 < 2; nt2++) {
                    int mc = sb * 16 + nt2 * 8;
                    float d[4] = {0.f, 0.f, 0.f, 0.f};
#pragma unroll
                    for (int k = 0; k < 8; k++) {
                        uint32_t bh0, bl0, bh1, bl1;
                        msp(ms[(mc + g) * MSP + k * 8 + c], bh0, bl0);
                        msp(ms[(mc + g) * MSP + k * 8 + c + 4], bh1, bl1);
                        mma8(d, ah[k], bh0, bh1);
                        mma8(d, ah[k], bl0, bl1);
                        mma8(d, al[k], bh0, bh1);
                    }
                    int col = ch * 128 + mc + 2 * c;
                    float2 v01 = {__expf(d[0] - mx) * inv0, __expf(d[1] - mx) * inv0};
                    float2 v23 = {__expf(d[2] - mx) * inv1, __expf(d[3] - mx) * inv1};
                    *(float2*)&fs[(size_t)(s0 * 4 + wrow + g) * MSZ + col] = v01;
                    *(float2*)&fs[(size_t)(s0 * 4 + wrow + g + 8) * MSZ + col] = v23;
                }
            }
            __syncthreads();
        }
    }
}

extern "C" void kernel_launch(void* const* d_in, const int* in_sizes, int n_in,
                              void* d_out, int out_size) {
    const float* x = (const float*)d_in[0];
    const int* uid = (const int*)d_in[1];
    const float* tab = (const float*)d_in[2];
    const float* Wp = (const float*)d_in[3];
    const float* bp = (const float*)d_in[4];
    const float* Wq = (const float*)d_in[5];
    const float* memp = (const float*)d_in[6];
    float* out = (float*)d_out;

    k_uid<<<1, 256>>>(uid);
    k_pe<<<BB, 128>>>(tab, Wp, bp);

    const int qg_smem = (2 * 64 * 36 + 2 * 32 * 132) * 4;
    cudaFuncSetAttribute(k_qgemm, cudaFuncAttributeMaxDynamicSharedMemorySize, qg_smem);
    dim3 g2(2, 2, BB);
    k_qgemm<<<g2, 256, qg_smem>>>(x, Wq);

    const int smem_bytes = (2 * 128 * MSP + 8 * 2 * 16 * ESP) * 4;
    cudaFuncSetAttribute(k_attn, cudaFuncAttributeMaxDynamicSharedMemorySize, smem_bytes);
    dim3 g3(4, BB);
    k_attn<<<g3, 256, smem_bytes>>>(memp, out);
}

// round 15
// speedup vs baseline: 1.7452x; 1.1561x over previous
#include <cuda_runtime.h>
#include <cstdint>

#define NUSERS 100000
#define E 64
#define P 128
#define NSHARD 16
#define MSZ 512
#define WD 64
#define RR 4
#define INSZ 256
#define BB 256
#define SS 128
#define IND 384
#define QO 256

#define MSP 68
#define ESP 20

__device__ float g_pe[BB * P];
__device__ float g_q[(size_t)BB * SS * QO];
__device__ int g_uid[BB];

__global__ void k_uid(const int* __restrict__ u) {
    int s = 2;
#pragma unroll
    for (int i = 0; i < 8; i++)
        if (u[2 * i + 1] != 0) s = 1;
    int b = blockIdx.x * blockDim.x + threadIdx.x;
    if (b < BB) g_uid[b] = u[b * s];
}

// tf32 exact hi/lo split (k_qgemm)
__device__ __forceinline__ void msp(float x, uint32_t& h, uint32_t& l) {
    h = __float_as_uint(x) & 0xFFFFE000u;
    l = __float_as_uint(x - __uint_as_float(h));
}
__device__ __forceinline__ void mma8(float d[4], const uint32_t a[4], uint32_t b0, uint32_t b1) {
    asm volatile(
        "mma.sync.aligned.m16n8k8.row.col.f32.tf32.tf32.f32 "
        "{%0,%1,%2,%3}, {%4,%5,%6,%7}, {%8,%9}, {%0,%1,%2,%3};"
        : "+f"(d[0]), "+f"(d[1]), "+f"(d[2]), "+f"(d[3])
        : "r"(a[0]), "r"(a[1]), "r"(a[2]), "r"(a[3]), "r"(b0), "r"(b1));
}
// bf16 k16 mma
__device__ __forceinline__ void mmab(float d[4], const uint32_t a[4], uint32_t b0, uint32_t b1) {
    asm volatile(
        "mma.sync.aligned.m16n8k16.row.col.f32.bf16.bf16.f32 "
        "{%0,%1,%2,%3}, {%4,%5,%6,%7}, {%8,%9}, {%0,%1,%2,%3};"
        : "+f"(d[0]), "+f"(d[1]), "+f"(d[2]), "+f"(d[3])
        : "r"(a[0]), "r"(a[1]), "r"(a[2]), "r"(a[3]), "r"(b0), "r"(b1));
}
// bf16 rn hi/lo split of a pair (x0 = even k -> low half)
__device__ __forceinline__ void bsp2(float x0, float x1, uint32_t& h, uint32_t& l) {
    asm("cvt.rn.bf16x2.f32 %0, %1, %2;" : "=r"(h) : "f"(x1), "f"(x0));
    float h0 = __uint_as_float(h << 16);
    float h1 = __uint_as_float(h & 0xFFFF0000u);
    float l0 = x0 - h0, l1 = x1 - h1;
    asm("cvt.rn.bf16x2.f32 %0, %1, %2;" : "=r"(l) : "f"(l1), "f"(l0));
}
__device__ __forceinline__ void bsp(float2 v, uint32_t& h, uint32_t& l) { bsp2(v.x, v.y, h, l); }

__device__ __forceinline__ uint32_t smem_u32(const void* p) {
    uint32_t a;
    asm("{ .reg .u64 t; cvta.to.shared.u64 t, %1; cvt.u32.u64 %0, t; }" : "=r"(a) : "l"(p));
    return a;
}
__device__ __forceinline__ void cpa16(uint32_t s, const void* g) {
    asm volatile("cp.async.ca.shared.global [%0], [%1], 16;" :: "r"(s), "l"(g));
}
__device__ __forceinline__ void cpcommit() { asm volatile("cp.async.commit_group;"); }
__device__ __forceinline__ void cpwait1() { asm volatile("cp.async.wait_group 1;"); }
__device__ __forceinline__ void cpwait0() { asm volatile("cp.async.wait_group 0;"); }

__global__ void k_pe(const float* __restrict__ tab, const float* __restrict__ Wp,
                     const float* __restrict__ bp) {
    __shared__ float ue[E];
    int b = blockIdx.x;
    int t = threadIdx.x;
    int uid = g_uid[b];
    if (t < E) ue[t] = tab[(size_t)uid * E + t];
    __syncthreads();
    float acc = bp[t];
#pragma unroll
    for (int e = 0; e < E; e++) acc += ue[e] * Wp[e * P + t];
    g_pe[b * P + t] = acc;
}

// --- q = concat(x, pe) @ Wq[sid]; 64x128 block (R14, unchanged) ---
__global__ __launch_bounds__(256) void k_qgemm(const float* __restrict__ x,
                                               const float* __restrict__ Wq) {
    extern __shared__ float qsm[];
    float* As = qsm;
    float* Bs = qsm + 2 * 64 * 36;
    int b = blockIdx.z;
    int n0 = blockIdx.x * 128, m0 = blockIdx.y * 64;
    int sid = ((unsigned)g_uid[b]) % NSHARD;
    const float* Wg = Wq + (size_t)sid * IND * QO;
    int tid = threadIdx.x;
    int lane = tid & 31, warp = tid >> 5;
    int g = lane >> 2, c = lane & 3;
    int wm = warp & 3, wn = warp >> 2;
    const float* xb = x + ((size_t)b * SS + m0) * INSZ;
    const float* pe = g_pe + b * P;
    uint32_t asb = smem_u32(As);
    uint32_t bsb = smem_u32(Bs);

    float d[8][4];
#pragma unroll
    for (int i = 0; i < 8; i++)
#pragma unroll
        for (int j = 0; j < 4; j++) d[i][j] = 0.f;

#define LOADTILE(t, buf)                                                                  \
    do {                                                                                  \
        int k0_ = (t) * 32;                                                               \
        for (int i = tid; i < 512; i += 256) {                                            \
            int row = i >> 3, k4 = (i & 7) * 4;                                           \
            const float* src = (k0_ < INSZ) ? &xb[row * INSZ + k0_ + k4]                  \
                                            : &pe[k0_ - INSZ + k4];                       \
            cpa16(asb + ((buf) * 64 * 36 + row * 36 + k4) * 4, src);                      \
        }                                                                                 \
        for (int i = tid; i < 1024; i += 256) {                                           \
            int kk = i >> 5, n4 = (i & 31) * 4;                                           \
            cpa16(bsb + ((buf) * 32 * 132 + kk * 132 + n4) * 4,                           \
                  &Wg[(size_t)(k0_ + kk) * QO + n0 + n4]);                                \
        }                                                                                 \
    } while (0)

    LOADTILE(0, 0);
    cpcommit();

    for (int t = 0; t < 12; t++) {
        int buf = t & 1;
        if (t < 11) {
            LOADTILE(t + 1, buf ^ 1);
            cpcommit();
            cpwait1();
        } else {
            cpwait0();
        }
        __syncthreads();
#pragma unroll
        for (int ks = 0; ks < 4; ks++) {
            uint32_t ah[4], al[4];
            msp(As[buf * 2304 + (wm * 16 + g) * 36 + ks * 8 + c], ah[0], al[0]);
            msp(As[buf * 2304 + (wm * 16 + g + 8) * 36 + ks * 8 + c], ah[1], al[1]);
            msp(As[buf * 2304 + (wm * 16 + g) * 36 + ks * 8 + c + 4], ah[2], al[2]);
            msp(As[buf * 2304 + (wm * 16 + g + 8) * 36 + ks * 8 + c + 4], ah[3], al[3]);
#pragma unroll
            for (int nt = 0; nt < 8; nt++) {
                int nn = wn * 64 + nt * 8;
                uint32_t bh0, bl0, bh1, bl1;
                msp(Bs[buf * 4224 + (ks * 8 + c) * 132 + nn + g], bh0, bl0);
                msp(Bs[buf * 4224 + (ks * 8 + c + 4) * 132 + nn + g], bh1, bl1);
                mma8(d[nt], ah, bh0, bh1);
                mma8(d[nt], ah, bl0, bl1);
                mma8(d[nt], al, bh0, bh1);
            }
        }
        __syncthreads();
    }
    float* qb = g_q + ((size_t)b * SS + m0) * QO + n0;
#pragma unroll
    for (int nt = 0; nt < 8; nt++) {
        int nn = wn * 64 + nt * 8 + 2 * c;
        float2 v01 = {d[nt][0], d[nt][1]};
        float2 v23 = {d[nt][2], d[nt][3]};
        *(float2*)&qb[(size_t)(wm * 16 + g) * QO + nn] = v01;
        *(float2*)&qb[(size_t)(wm * 16 + g + 8) * QO + nn] = v23;
    }
}

// ---- flash attention, bf16 k16 3-pass (R13 control flow) ----
__global__ __launch_bounds__(256, 2) void k_attn(const float* __restrict__ mem,
                                                 float* __restrict__ out) {
    extern __shared__ float sm[];
    float* qs = sm;
    float* ms = qs + 128 * MSP;
    float* es = ms + 128 * MSP;

    int tid = threadIdx.x;
    int lane = tid & 31, warp = tid >> 5;
    int g = lane >> 2, c = lane & 3;
    int b = blockIdx.y;
    int s0 = blockIdx.x * 32;
    int sid = ((unsigned)g_uid[b]) % NSHARD;
    const float* M = mem + (size_t)sid * MSZ * WD;
    float* ew = es + warp * (16 * ESP);
    int wrow = warp * 16;

    const float* qsrc = g_q + ((size_t)b * SS + s0) * QO;
    for (int i = tid; i < 128 * 16; i += 256) {
        int row = i >> 4, w4 = (i & 15) * 4;
        float4 v = *(const float4*)&qsrc[(size_t)(row >> 2) * QO + (row & 3) * WD + w4];
        *(float4*)&qs[row * MSP + w4] = v;
    }

    uint32_t ahp[4][4], alp[4][4];
    float acc[8][4];
#pragma unroll
    for (int nt = 0; nt < 8; nt++)
#pragma unroll
        for (int j = 0; j < 4; j++) acc[nt][j] = 0.f;
    float mx = -1e30f, sm0 = 0.f, sm1 = 0.f;

    for (int ch = 0; ch < 4; ch++) {
        for (int i = tid; i < 128 * 16; i += 256) {
            int m = i >> 4, w4 = (i & 15) * 4;
            *(float4*)&ms[m * MSP + w4] = *(const float4*)&M[(size_t)(ch * 128 + m) * WD + w4];
        }
        __syncthreads();
        if (ch == 0) {
#pragma unroll
            for (int ks = 0; ks < 4; ks++) {
                float2 x0 = *(const float2*)&qs[(wrow + g) * MSP + ks * 16 + 2 * c];
                float2 x1 = *(const float2*)&qs[(wrow + g + 8) * MSP + ks * 16 + 2 * c];
                float2 x2 = *(const float2*)&qs[(wrow + g) * MSP + ks * 16 + 2 * c + 8];
                float2 x3 = *(const float2*)&qs[(wrow + g + 8) * MSP + ks * 16 + 2 * c + 8];
                bsp(x0, ahp[ks][0], alp[ks][0]);
                bsp(x1, ahp[ks][1], alp[ks][1]);
                bsp(x2, ahp[ks][2], alp[ks][2]);
                bsp(x3, ahp[ks][3], alp[ks][3]);
            }
        }
        for (int sb = 0; sb < 8; sb++) {
            float e[2][4];
#pragma unroll
            for (int nt2 = 0; nt2 < 2; nt2++) {
                int mc = sb * 16 + nt2 * 8;
                float d0[4] = {0.f, 0.f, 0.f, 0.f};
                float d1[4] = {0.f, 0.f, 0.f, 0.f};
#pragma unroll
                for (int ks = 0; ks < 4; ks += 2) {
                    {
                        float2 y0 = *(const float2*)&ms[(mc + g) * MSP + ks * 16 + 2 * c];
                        float2 y1 = *(const float2*)&ms[(mc + g) * MSP + ks * 16 + 2 * c + 8];
                        uint32_t bh0, bl0, bh1, bl1;
                        bsp(y0, bh0, bl0);
                        bsp(y1, bh1, bl1);
                        mmab(d0, ahp[ks], bh0, bh1);
                        mmab(d0, ahp[ks], bl0, bl1);
                        mmab(d0, alp[ks], bh0, bh1);
                    }
                    {
                        float2 y0 = *(const float2*)&ms[(mc + g) * MSP + (ks + 1) * 16 + 2 * c];
                        float2 y1 = *(const float2*)&ms[(mc + g) * MSP + (ks + 1) * 16 + 2 * c + 8];
                        uint32_t bh0, bl0, bh1, bl1;
                        bsp(y0, bh0, bl0);
                        bsp(y1, bh1, bl1);
                        mmab(d1, ahp[ks + 1], bh0, bh1);
                        mmab(d1, ahp[ks + 1], bl0, bl1);
                        mmab(d1, alp[ks + 1], bh0, bh1);
                    }
                }
#pragma unroll
                for (int j = 0; j < 4; j++) e[nt2][j] = d0[j] + d1[j];
            }
            // warp-shared max, rare bit-exact rescale
            float m = fmaxf(fmaxf(fmaxf(e[0][0], e[0][1]), fmaxf(e[0][2], e[0][3])),
                            fmaxf(fmaxf(e[1][0], e[1][1]), fmaxf(e[1][2], e[1][3])));
#pragma unroll
            for (int o = 16; o > 0; o >>= 1) m = fmaxf(m, __shfl_xor_sync(0xffffffffu, m, o));
            if (m > mx) {
                float sc = __expf(mx - m);
                sm0 *= sc; sm1 *= sc;
#pragma unroll
                for (int nt = 0; nt < 8; nt++) {
                    acc[nt][0] *= sc; acc[nt][1] *= sc;
                    acc[nt][2] *= sc; acc[nt][3] *= sc;
                }
                mx = m;
            }
#pragma unroll
            for (int nt2 = 0; nt2 < 2; nt2++) {
                float e0 = __expf(e[nt2][0] - mx);
                float e1 = __expf(e[nt2][1] - mx);
                float e2 = __expf(e[nt2][2] - mx);
                float e3 = __expf(e[nt2][3] - mx);
                sm0 += e0 + e1; sm1 += e2 + e3;
                int col = nt2 * 8 + 2 * c;
                float2 v01 = {e0, e1};
                float2 v23 = {e2, e3};
                *(float2*)&ew[g * ESP + col] = v01;
                *(float2*)&ew[(g + 8) * ESP + col] = v23;
            }
            __syncwarp();
            // phase 2: bf16 k16, weights hi/lo, mem hi/lo (3-pass)
            {
                uint32_t awh[4], awl[4];
                float2 w0 = *(const float2*)&ew[g * ESP + 2 * c];
                float2 w1 = *(const float2*)&ew[(g + 8) * ESP + 2 * c];
                float2 w2 = *(const float2*)&ew[g * ESP + 2 * c + 8];
                float2 w3 = *(const float2*)&ew[(g + 8) * ESP + 2 * c + 8];
                bsp(w0, awh[0], awl[0]);
                bsp(w1, awh[1], awl[1]);
                bsp(w2, awh[2], awl[2]);
                bsp(w3, awh[3], awl[3]);
                int mb = sb * 16;
#pragma unroll
                for (int nt = 0; nt < 8; nt++) {
                    int w0c = nt * 8 + g;
                    float b00 = ms[(mb + 2 * c) * MSP + w0c];
                    float b01 = ms[(mb + 2 * c + 1) * MSP + w0c];
                    float b10 = ms[(mb + 2 * c + 8) * MSP + w0c];
                    float b11 = ms[(mb + 2 * c + 9) * MSP + w0c];
                    uint32_t bh0, bl0, bh1, bl1;
                    bsp2(b00, b01, bh0, bl0);
                    bsp2(b10, b11, bh1, bl1);
                    mmab(acc[nt], awh, bh0, bh1);
                    mmab(acc[nt], awh, bl0, bl1);
                    mmab(acc[nt], awl, bh0, bh1);
                }
            }
            __syncwarp();
        }
        __syncthreads();
    }

    sm0 += __shfl_xor_sync(0xffffffffu, sm0, 1);
    sm0 += __shfl_xor_sync(0xffffffffu, sm0, 2);
    sm1 += __shfl_xor_sync(0xffffffffu, sm1, 1);
    sm1 += __shfl_xor_sync(0xffffffffu, sm1, 2);
    float inv0 = 1.f / sm0, inv1 = 1.f / sm1;
    float* ob = out + ((size_t)b * 512 + s0 * 4) * WD;
#pragma unroll
    for (int nt = 0; nt < 8; nt++) {
        int col = nt * 8 + 2 * c;
        float2 v01 = {acc[nt][0] * inv0, acc[nt][1] * inv0};
        float2 v23 = {acc[nt][2] * inv1, acc[nt][3] * inv1};
        *(float2*)&ob[(size_t)(wrow + g) * WD + col] = v01;
        *(float2*)&ob[(size_t)(wrow + g + 8) * WD + col] = v23;
    }

    // ---- fused final_state (b == B-1): recompute scores bf16, normalize ----
    if (b == BB - 1) {
        float* fs = out + (size_t)BB * SS * RR * WD;
        for (int ch = 0; ch < 4; ch++) {
            for (int i = tid; i < 128 * 16; i += 256) {
                int m = i >> 4, w4 = (i & 15) * 4;
                *(float4*)&ms[m * MSP + w4] = *(const float4*)&M[(size_t)(ch * 128 + m) * WD + w4];
            }
            __syncthreads();
            for (int sb = 0; sb < 8; sb++) {
#pragma unroll
                for (int nt2 = 0; nt2 < 2; nt2++) {
                    int mc = sb * 16 + nt2 * 8;
                    float d[4] = {0.f, 0.f, 0.f, 0.f};
#pragma unroll
                    for (int ks = 0; ks < 4; ks++) {
                        float2 y0 = *(const float2*)&ms[(mc + g) * MSP + ks * 16 + 2 * c];
                        float2 y1 = *(const float2*)&ms[(mc + g) * MSP + ks * 16 + 2 * c + 8];
                        uint32_t bh0, bl0, bh1, bl1;
                        bsp(y0, bh0, bl0);
                        bsp(y1, bh1, bl1);
                        mmab(d, ahp[ks], bh0, bh1);
                        mmab(d, ahp[ks], bl0, bl1);
                        mmab(d, alp[ks], bh0, bh1);
                    }
                    int col = ch * 128 + mc + 2 * c;
                    float2 v01 = {__expf(d[0] - mx) * inv0, __expf(d[1] - mx) * inv0};
                    float2 v23 = {__expf(d[2] - mx) * inv1, __expf(d[3] - mx) * inv1};
                    *(float2*)&fs[(size_t)(s0 * 4 + wrow + g) * MSZ + col] = v01;
                    *(float2*)&fs[(size_t)(s0 * 4 + wrow + g + 8) * MSZ + col] = v23;
                }
            }
            __syncthreads();
        }
    }
}

extern "C" void kernel_launch(void* const* d_in, const int* in_sizes, int n_in,
                              void* d_out, int out_size) {
    const float* x = (const float*)d_in[0];
    const int* uid = (const int*)d_in[1];
    const float* tab = (const float*)d_in[2];
    const float* Wp = (const float*)d_in[3];
    const float* bp = (const float*)d_in[4];
    const float* Wq = (const float*)d_in[5];
    const float* memp = (const float*)d_in[6];
    float* out = (float*)d_out;

    k_uid<<<1, 256>>>(uid);
    k_pe<<<BB, 128>>>(tab, Wp, bp);

    const int qg_smem = (2 * 64 * 36 + 2 * 32 * 132) * 4;
    cudaFuncSetAttribute(k_qgemm, cudaFuncAttributeMaxDynamicSharedMemorySize, qg_smem);
    dim3 g2(2, 2, BB);
    k_qgemm<<<g2, 256, qg_smem>>>(x, Wq);

    const int smem_bytes = (2 * 128 * MSP + 8 * 16 * ESP) * 4;
    cudaFuncSetAttribute(k_attn, cudaFuncAttributeMaxDynamicSharedMemorySize, smem_bytes);
    dim3 g3(4, BB);
    k_attn<<<g3, 256, smem_bytes>>>(memp, out);
}

// round 16
// speedup vs baseline: 1.8661x; 1.0693x over previous
#include <cuda_runtime.h>
#include <cstdint>

#define NUSERS 100000
#define E 64
#define P 128
#define NSHARD 16
#define MSZ 512
#define WD 64
#define RR 4
#define INSZ 256
#define BB 256
#define SS 128
#define IND 384
#define QO 256

#define ESP 20
#define MH_STRIDE 36
#define MT_STRIDE 68

__device__ float g_pe[BB * P];
__device__ float g_q[(size_t)BB * SS * QO];
__device__ int g_uid[BB];
// packed bf16x2 hi/lo splits of mem, two orientations
__device__ uint32_t g_mh[NSHARD * MSZ * 32];   // [sid][m][w/2]
__device__ uint32_t g_ml[NSHARD * MSZ * 32];
__device__ uint32_t g_mhT[NSHARD * WD * 256];  // [sid][w][m/2]
__device__ uint32_t g_mlT[NSHARD * WD * 256];

__global__ void k_uid(const int* __restrict__ u) {
    int s = 2;
#pragma unroll
    for (int i = 0; i < 8; i++)
        if (u[2 * i + 1] != 0) s = 1;
    int b = blockIdx.x * blockDim.x + threadIdx.x;
    if (b < BB) g_uid[b] = u[b * s];
}

__device__ __forceinline__ void msp(float x, uint32_t& h, uint32_t& l) {
    h = __float_as_uint(x) & 0xFFFFE000u;
    l = __float_as_uint(x - __uint_as_float(h));
}
__device__ __forceinline__ void mma8(float d[4], const uint32_t a[4], uint32_t b0, uint32_t b1) {
    asm volatile(
        "mma.sync.aligned.m16n8k8.row.col.f32.tf32.tf32.f32 "
        "{%0,%1,%2,%3}, {%4,%5,%6,%7}, {%8,%9}, {%0,%1,%2,%3};"
        : "+f"(d[0]), "+f"(d[1]), "+f"(d[2]), "+f"(d[3])
        : "r"(a[0]), "r"(a[1]), "r"(a[2]), "r"(a[3]), "r"(b0), "r"(b1));
}
__device__ __forceinline__ void mmab(float d[4], const uint32_t a[4], uint32_t b0, uint32_t b1) {
    asm volatile(
        "mma.sync.aligned.m16n8k16.row.col.f32.bf16.bf16.f32 "
        "{%0,%1,%2,%3}, {%4,%5,%6,%7}, {%8,%9}, {%0,%1,%2,%3};"
        : "+f"(d[0]), "+f"(d[1]), "+f"(d[2]), "+f"(d[3])
        : "r"(a[0]), "r"(a[1]), "r"(a[2]), "r"(a[3]), "r"(b0), "r"(b1));
}
__device__ __forceinline__ void bsp2(float x0, float x1, uint32_t& h, uint32_t& l) {
    asm("cvt.rn.bf16x2.f32 %0, %1, %2;" : "=r"(h) : "f"(x1), "f"(x0));
    float h0 = __uint_as_float(h << 16);
    float h1 = __uint_as_float(h & 0xFFFF0000u);
    float l0 = x0 - h0, l1 = x1 - h1;
    asm("cvt.rn.bf16x2.f32 %0, %1, %2;" : "=r"(l) : "f"(l1), "f"(l0));
}
__device__ __forceinline__ void bsp(float2 v, uint32_t& h, uint32_t& l) { bsp2(v.x, v.y, h, l); }

__device__ __forceinline__ uint32_t smem_u32(const void* p) {
    uint32_t a;
    asm("{ .reg .u64 t; cvta.to.shared.u64 t, %1; cvt.u32.u64 %0, t; }" : "=r"(a) : "l"(p));
    return a;
}
__device__ __forceinline__ void cpa16(uint32_t s, const void* g) {
    asm volatile("cp.async.ca.shared.global [%0], [%1], 16;" :: "r"(s), "l"(g));
}
__device__ __forceinline__ void cpcommit() { asm volatile("cp.async.commit_group;"); }
__device__ __forceinline__ void cpwait1() { asm volatile("cp.async.wait_group 1;"); }
__device__ __forceinline__ void cpwait0() { asm volatile("cp.async.wait_group 0;"); }

// --- pre-split mem into packed bf16x2 hi/lo, both orientations (once, tiny) ---
__global__ void k_split(const float* __restrict__ mem) {
    int i = blockIdx.x * blockDim.x + threadIdx.x;
    if (i >= NSHARD * MSZ * 32) return;
    // layout1: [sid][m][wp]
    {
        int wp = i & 31, m = (i >> 5) & 511, sid = i >> 14;
        const float* src = mem + ((size_t)sid * MSZ + m) * WD + 2 * wp;
        uint32_t h, l;
        bsp2(src[0], src[1], h, l);
        g_mh[i] = h;
        g_ml[i] = l;
    }
    // layout2: [sid][w][mp]  (same total count: 16*64*256)
    {
        int mp = i & 255, w = (i >> 8) & 63, sid = i >> 14;
        const float* base = mem + (size_t)sid * MSZ * WD;
        uint32_t h, l;
        bsp2(base[(size_t)(2 * mp) * WD + w], base[(size_t)(2 * mp + 1) * WD + w], h, l);
        g_mhT[i] = h;
        g_mlT[i] = l;
    }
}

__global__ void k_pe(const float* __restrict__ tab, const float* __restrict__ Wp,
                     const float* __restrict__ bp) {
    __shared__ float ue[E];
    int b = blockIdx.x;
    int t = threadIdx.x;
    int uid = g_uid[b];
    if (t < E) ue[t] = tab[(size_t)uid * E + t];
    __syncthreads();
    float acc = bp[t];
#pragma unroll
    for (int e = 0; e < E; e++) acc += ue[e] * Wp[e * P + t];
    g_pe[b * P + t] = acc;
}

// --- q = concat(x, pe) @ Wq[sid]; 64x128 block (unchanged) ---
__global__ __launch_bounds__(256) void k_qgemm(const float* __restrict__ x,
                                               const float* __restrict__ Wq) {
    extern __shared__ float qsm[];
    float* As = qsm;
    float* Bs = qsm + 2 * 64 * 36;
    int b = blockIdx.z;
    int n0 = blockIdx.x * 128, m0 = blockIdx.y * 64;
    int sid = ((unsigned)g_uid[b]) % NSHARD;
    const float* Wg = Wq + (size_t)sid * IND * QO;
    int tid = threadIdx.x;
    int lane = tid & 31, warp = tid >> 5;
    int g = lane >> 2, c = lane & 3;
    int wm = warp & 3, wn = warp >> 2;
    const float* xb = x + ((size_t)b * SS + m0) * INSZ;
    const float* pe = g_pe + b * P;
    uint32_t asb = smem_u32(As);
    uint32_t bsb = smem_u32(Bs);

    float d[8][4];
#pragma unroll
    for (int i = 0; i < 8; i++)
#pragma unroll
        for (int j = 0; j < 4; j++) d[i][j] = 0.f;

#define LOADTILE(t, buf)                                                                  \
    do {                                                                                  \
        int k0_ = (t) * 32;                                                               \
        for (int i = tid; i < 512; i += 256) {                                            \
            int row = i >> 3, k4 = (i & 7) * 4;                                           \
            const float* src = (k0_ < INSZ) ? &xb[row * INSZ + k0_ + k4]                  \
                                            : &pe[k0_ - INSZ + k4];                       \
            cpa16(asb + ((buf) * 64 * 36 + row * 36 + k4) * 4, src);                      \
        }                                                                                 \
        for (int i = tid; i < 1024; i += 256) {                                           \
            int kk = i >> 5, n4 = (i & 31) * 4;                                           \
            cpa16(bsb + ((buf) * 32 * 132 + kk * 132 + n4) * 4,                           \
                  &Wg[(size_t)(k0_ + kk) * QO + n0 + n4]);                                \
        }                                                                                 \
    } while (0)

    LOADTILE(0, 0);
    cpcommit();

    for (int t = 0; t < 12; t++) {
        int buf = t & 1;
        if (t < 11) {
            LOADTILE(t + 1, buf ^ 1);
            cpcommit();
            cpwait1();
        } else {
            cpwait0();
        }
        __syncthreads();
#pragma unroll
        for (int ks = 0; ks < 4; ks++) {
            uint32_t ah[4], al[4];
            msp(As[buf * 2304 + (wm * 16 + g) * 36 + ks * 8 + c], ah[0], al[0]);
            msp(As[buf * 2304 + (wm * 16 + g + 8) * 36 + ks * 8 + c], ah[1], al[1]);
            msp(As[buf * 2304 + (wm * 16 + g) * 36 + ks * 8 + c + 4], ah[2], al[2]);
            msp(As[buf * 2304 + (wm * 16 + g + 8) * 36 + ks * 8 + c + 4], ah[3], al[3]);
#pragma unroll
            for (int nt = 0; nt < 8; nt++) {
                int nn = wn * 64 + nt * 8;
                uint32_t bh0, bl0, bh1, bl1;
                msp(Bs[buf * 4224 + (ks * 8 + c) * 132 + nn + g], bh0, bl0);
                msp(Bs[buf * 4224 + (ks * 8 + c + 4) * 132 + nn + g], bh1, bl1);
                mma8(d[nt], ah, bh0, bh1);
                mma8(d[nt], ah, bl0, bl1);
                mma8(d[nt], al, bh0, bh1);
            }
        }
        __syncthreads();
    }
    float* qb = g_q + ((size_t)b * SS + m0) * QO + n0;
#pragma unroll
    for (int nt = 0; nt < 8; nt++) {
        int nn = wn * 64 + nt * 8 + 2 * c;
        float2 v01 = {d[nt][0], d[nt][1]};
        float2 v23 = {d[nt][2], d[nt][3]};
        *(float2*)&qb[(size_t)(wm * 16 + g) * QO + nn] = v01;
        *(float2*)&qb[(size_t)(wm * 16 + g + 8) * QO + nn] = v23;
    }
}

// ---- flash attention, bf16 k16, pre-split B (zero cvt in hot loops) ----
__global__ __launch_bounds__(256, 2) void k_attn(float* __restrict__ out) {
    extern __shared__ uint32_t smu[];
    uint32_t* msh = smu;                    // [128][36]
    uint32_t* msl = msh + 128 * MH_STRIDE;  // [128][36]
    uint32_t* mshT = msl + 128 * MH_STRIDE; // [64][68]
    uint32_t* mslT = mshT + 64 * MT_STRIDE; // [64][68]
    float* es = (float*)(mslT + 64 * MT_STRIDE);

    int tid = threadIdx.x;
    int lane = tid & 31, warp = tid >> 5;
    int g = lane >> 2, c = lane & 3;
    int b = blockIdx.y;
    int s0 = blockIdx.x * 32;
    int sid = ((unsigned)g_uid[b]) % NSHARD;
    float* ew = es + warp * (16 * ESP);
    int wrow = warp * 16;

    const uint32_t* Mh = g_mh + (size_t)sid * MSZ * 32;
    const uint32_t* Ml = g_ml + (size_t)sid * MSZ * 32;
    const uint32_t* MhT = g_mhT + (size_t)sid * WD * 256;
    const uint32_t* MlT = g_mlT + (size_t)sid * WD * 256;

    // q fragments: direct from global (once)
    uint32_t ahp[4][4], alp[4][4];
    {
        const float* qsrc = g_q + ((size_t)b * SS + s0) * QO;
        int r0 = wrow + g, r1 = wrow + g + 8;
        const float* qb0 = qsrc + (size_t)(r0 >> 2) * QO + (r0 & 3) * WD;
        const float* qb1 = qsrc + (size_t)(r1 >> 2) * QO + (r1 & 3) * WD;
#pragma unroll
        for (int ks = 0; ks < 4; ks++) {
            float2 x0 = *(const float2*)&qb0[ks * 16 + 2 * c];
            float2 x1 = *(const float2*)&qb1[ks * 16 + 2 * c];
            float2 x2 = *(const float2*)&qb0[ks * 16 + 2 * c + 8];
            float2 x3 = *(const float2*)&qb1[ks * 16 + 2 * c + 8];
            bsp(x0, ahp[ks][0], alp[ks][0]);
            bsp(x1, ahp[ks][1], alp[ks][1]);
            bsp(x2, ahp[ks][2], alp[ks][2]);
            bsp(x3, ahp[ks][3], alp[ks][3]);
        }
    }

    float acc[8][4];
#pragma unroll
    for (int nt = 0; nt < 8; nt++)
#pragma unroll
        for (int j = 0; j < 4; j++) acc[nt][j] = 0.f;
    float mx = -1e30f, sm0 = 0.f, sm1 = 0.f;

    for (int ch = 0; ch < 4; ch++) {
        // stage packed hi/lo tiles
        for (int i = tid; i < 128 * 8; i += 256) {
            int m = i >> 3, q4 = (i & 7) * 4;
            size_t go = ((size_t)ch * 128 + m) * 32 + q4;
            *(uint4*)&msh[m * MH_STRIDE + q4] = *(const uint4*)&Mh[go];
            *(uint4*)&msl[m * MH_STRIDE + q4] = *(const uint4*)&Ml[go];
        }
        for (int i = tid; i < 64 * 16; i += 256) {
            int w = i >> 4, q4 = (i & 15) * 4;
            size_t go = (size_t)w * 256 + ch * 64 + q4;
            *(uint4*)&mshT[w * MT_STRIDE + q4] = *(const uint4*)&MhT[go];
            *(uint4*)&mslT[w * MT_STRIDE + q4] = *(const uint4*)&MlT[go];
        }
        __syncthreads();

        for (int sb = 0; sb < 8; sb++) {
            float e[2][4];
#pragma unroll
            for (int nt2 = 0; nt2 < 2; nt2++) {
                int mc = sb * 16 + nt2 * 8;
                float d0[4] = {0.f, 0.f, 0.f, 0.f};
                float d1[4] = {0.f, 0.f, 0.f, 0.f};
#pragma unroll
                for (int ks = 0; ks < 4; ks += 2) {
                    {
                        const uint32_t* rh = &msh[(mc + g) * MH_STRIDE + ks * 8 + c];
                        const uint32_t* rl = &msl[(mc + g) * MH_STRIDE + ks * 8 + c];
                        uint32_t bh0 = rh[0], bh1 = rh[4];
                        uint32_t bl0 = rl[0], bl1 = rl[4];
                        mmab(d0, ahp[ks], bh0, bh1);
                        mmab(d0, ahp[ks], bl0, bl1);
                        mmab(d0, alp[ks], bh0, bh1);
                    }
                    {
                        const uint32_t* rh = &msh[(mc + g) * MH_STRIDE + (ks + 1) * 8 + c];
                        const uint32_t* rl = &msl[(mc + g) * MH_STRIDE + (ks + 1) * 8 + c];
                        uint32_t bh0 = rh[0], bh1 = rh[4];
                        uint32_t bl0 = rl[0], bl1 = rl[4];
                        mmab(d1, ahp[ks + 1], bh0, bh1);
                        mmab(d1, ahp[ks + 1], bl0, bl1);
                        mmab(d1, alp[ks + 1], bh0, bh1);
                    }
                }
#pragma unroll
                for (int j = 0; j < 4; j++) e[nt2][j] = d0[j] + d1[j];
            }
            // warp-shared max, rare bit-exact rescale
            float m = fmaxf(fmaxf(fmaxf(e[0][0], e[0][1]), fmaxf(e[0][2], e[0][3])),
                            fmaxf(fmaxf(e[1][0], e[1][1]), fmaxf(e[1][2], e[1][3])));
#pragma unroll
            for (int o = 16; o > 0; o >>= 1) m = fmaxf(m, __shfl_xor_sync(0xffffffffu, m, o));
            if (m > mx) {
                float sc = __expf(mx - m);
                sm0 *= sc; sm1 *= sc;
#pragma unroll
                for (int nt = 0; nt < 8; nt++) {
                    acc[nt][0] *= sc; acc[nt][1] *= sc;
                    acc[nt][2] *= sc; acc[nt][3] *= sc;
                }
                mx = m;
            }
#pragma unroll
            for (int nt2 = 0; nt2 < 2; nt2++) {
                float e0 = __expf(e[nt2][0] - mx);
                float e1 = __expf(e[nt2][1] - mx);
                float e2 = __expf(e[nt2][2] - mx);
                float e3 = __expf(e[nt2][3] - mx);
                sm0 += e0 + e1; sm1 += e2 + e3;
                int col = nt2 * 8 + 2 * c;
                float2 v01 = {e0, e1};
                float2 v23 = {e2, e3};
                *(float2*)&ew[g * ESP + col] = v01;
                *(float2*)&ew[(g + 8) * ESP + col] = v23;
            }
            __syncwarp();
            // phase 2: weights hi/lo (only in-loop split), mem from T arrays
            {
                uint32_t awh[4], awl[4];
                float2 w0 = *(const float2*)&ew[g * ESP + 2 * c];
                float2 w1 = *(const float2*)&ew[(g + 8) * ESP + 2 * c];
                float2 w2 = *(const float2*)&ew[g * ESP + 2 * c + 8];
                float2 w3 = *(const float2*)&ew[(g + 8) * ESP + 2 * c + 8];
                bsp(w0, awh[0], awl[0]);
                bsp(w1, awh[1], awl[1]);
                bsp(w2, awh[2], awl[2]);
                bsp(w3, awh[3], awl[3]);
#pragma unroll
                for (int nt = 0; nt < 8; nt++) {
                    int w0c = nt * 8 + g;
                    const uint32_t* rh = &mshT[w0c * MT_STRIDE + sb * 8 + c];
                    const uint32_t* rl = &mslT[w0c * MT_STRIDE + sb * 8 + c];
                    uint32_t bh0 = rh[0], bh1 = rh[4];
                    uint32_t bl0 = rl[0], bl1 = rl[4];
                    mmab(acc[nt], awh, bh0, bh1);
                    mmab(acc[nt], awh, bl0, bl1);
                    mmab(acc[nt], awl, bh0, bh1);
                }
            }
            __syncwarp();
        }
        __syncthreads();
    }

    sm0 += __shfl_xor_sync(0xffffffffu, sm0, 1);
    sm0 += __shfl_xor_sync(0xffffffffu, sm0, 2);
    sm1 += __shfl_xor_sync(0xffffffffu, sm1, 1);
    sm1 += __shfl_xor_sync(0xffffffffu, sm1, 2);
    float inv0 = 1.f / sm0, inv1 = 1.f / sm1;
    float* ob = out + ((size_t)b * 512 + s0 * 4) * WD;
#pragma unroll
    for (int nt = 0; nt < 8; nt++) {
        int col = nt * 8 + 2 * c;
        float2 v01 = {acc[nt][0] * inv0, acc[nt][1] * inv0};
        float2 v23 = {acc[nt][2] * inv1, acc[nt][3] * inv1};
        *(float2*)&ob[(size_t)(wrow + g) * WD + col] = v01;
        *(float2*)&ob[(size_t)(wrow + g + 8) * WD + col] = v23;
    }

    // ---- fused final_state (b == B-1): recompute scores, normalize ----
    if (b == BB - 1) {
        float* fs = out + (size_t)BB * SS * RR * WD;
        for (int ch = 0; ch < 4; ch++) {
            for (int i = tid; i < 128 * 8; i += 256) {
                int m = i >> 3, q4 = (i & 7) * 4;
                size_t go = ((size_t)ch * 128 + m) * 32 + q4;
                *(uint4*)&msh[m * MH_STRIDE + q4] = *(const uint4*)&Mh[go];
                *(uint4*)&msl[m * MH_STRIDE + q4] = *(const uint4*)&Ml[go];
            }
            __syncthreads();
            for (int sb = 0; sb < 8; sb++) {
#pragma unroll
                for (int nt2 = 0; nt2 < 2; nt2++) {
                    int mc = sb * 16 + nt2 * 8;
                    float d[4] = {0.f, 0.f, 0.f, 0.f};
#pragma unroll
                    for (int ks = 0; ks < 4; ks++) {
                        const uint32_t* rh = &msh[(mc + g) * MH_STRIDE + ks * 8 + c];
                        const uint32_t* rl = &msl[(mc + g) * MH_STRIDE + ks * 8 + c];
                        uint32_t bh0 = rh[0], bh1 = rh[4];
                        uint32_t bl0 = rl[0], bl1 = rl[4];
                        mmab(d, ahp[ks], bh0, bh1);
                        mmab(d, ahp[ks], bl0, bl1);
                        mmab(d, alp[ks], bh0, bh1);
                    }
                    int col = ch * 128 + mc + 2 * c;
                    float2 v01 = {__expf(d[0] - mx) * inv0, __expf(d[1] - mx) * inv0};
                    float2 v23 = {__expf(d[2] - mx) * inv1, __expf(d[3] - mx) * inv1};
                    *(float2*)&fs[(size_t)(s0 * 4 + wrow + g) * MSZ + col] = v01;
                    *(float2*)&fs[(size_t)(s0 * 4 + wrow + g + 8) * MSZ + col] = v23;
                }
            }
            __syncthreads();
        }
    }
}

extern "C" void kernel_launch(void* const* d_in, const int* in_sizes, int n_in,
                              void* d_out, int out_size) {
    const float* x = (const float*)d_in[0];
    const int* uid = (const int*)d_in[1];
    const float* tab = (const float*)d_in[2];
    const float* Wp = (const float*)d_in[3];
    const float* bp = (const float*)d_in[4];
    const float* Wq = (const float*)d_in[5];
    const float* memp = (const float*)d_in[6];
    float* out = (float*)d_out;

    k_uid<<<1, 256>>>(uid);
    k_split<<<(NSHARD * MSZ * 32 + 255) / 256, 256>>>(memp);
    k_pe<<<BB, 128>>>(tab, Wp, bp);

    const int qg_smem = (2 * 64 * 36 + 2 * 32 * 132) * 4;
    cudaFuncSetAttribute(k_qgemm, cudaFuncAttributeMaxDynamicSharedMemorySize, qg_smem);
    dim3 g2(2, 2, BB);
    k_qgemm<<<g2, 256, qg_smem>>>(x, Wq);

    const int at_smem = (2 * 128 * MH_STRIDE + 2 * 64 * MT_STRIDE + 8 * 16 * ESP) * 4;
    cudaFuncSetAttribute(k_attn, cudaFuncAttributeMaxDynamicSharedMemorySize, at_smem);
    dim3 g3(4, BB);
    k_attn<<<g3, 256, at_smem>>>(out);
}

// round 17
// speedup vs baseline: 1.9959x; 1.0695x over previous
#include <cuda_runtime.h>
#include <cstdint>

#define NUSERS 100000
#define E 64
#define P 128
#define NSHARD 16
#define MSZ 512
#define WD 64
#define RR 4
#define INSZ 256
#define BB 256
#define SS 128
#define IND 384
#define QO 256

#define ESP 20
#define MH_STRIDE 36
#define MT_STRIDE 68
#define AQ_STRIDE 20
#define BQ_STRIDE 132

__device__ float g_pe[BB * P];
__device__ float g_q[(size_t)BB * SS * QO];
__device__ int g_uid[BB];
// packed bf16x2 hi/lo splits of mem, two orientations
__device__ uint32_t g_mh[NSHARD * MSZ * 32];   // [sid][m][w/2]
__device__ uint32_t g_ml[NSHARD * MSZ * 32];
__device__ uint32_t g_mhT[NSHARD * WD * 256];  // [sid][w][m/2]
__device__ uint32_t g_mlT[NSHARD * WD * 256];
// packed bf16x2 hi/lo splits of Wq: [sid][k/2][n]
__device__ uint32_t g_wh[NSHARD * (IND / 2) * QO];
__device__ uint32_t g_wl[NSHARD * (IND / 2) * QO];

__global__ void k_uid(const int* __restrict__ u) {
    int s = 2;
#pragma unroll
    for (int i = 0; i < 8; i++)
        if (u[2 * i + 1] != 0) s = 1;
    int b = blockIdx.x * blockDim.x + threadIdx.x;
    if (b < BB) g_uid[b] = u[b * s];
}

__device__ __forceinline__ void mmab(float d[4], const uint32_t a[4], uint32_t b0, uint32_t b1) {
    asm volatile(
        "mma.sync.aligned.m16n8k16.row.col.f32.bf16.bf16.f32 "
        "{%0,%1,%2,%3}, {%4,%5,%6,%7}, {%8,%9}, {%0,%1,%2,%3};"
        : "+f"(d[0]), "+f"(d[1]), "+f"(d[2]), "+f"(d[3])
        : "r"(a[0]), "r"(a[1]), "r"(a[2]), "r"(a[3]), "r"(b0), "r"(b1));
}
__device__ __forceinline__ void bsp2(float x0, float x1, uint32_t& h, uint32_t& l) {
    asm("cvt.rn.bf16x2.f32 %0, %1, %2;" : "=r"(h) : "f"(x1), "f"(x0));
    float h0 = __uint_as_float(h << 16);
    float h1 = __uint_as_float(h & 0xFFFF0000u);
    float l0 = x0 - h0, l1 = x1 - h1;
    asm("cvt.rn.bf16x2.f32 %0, %1, %2;" : "=r"(l) : "f"(l1), "f"(l0));
}
__device__ __forceinline__ void bsp(float2 v, uint32_t& h, uint32_t& l) { bsp2(v.x, v.y, h, l); }

__device__ __forceinline__ uint32_t smem_u32(const void* p) {
    uint32_t a;
    asm("{ .reg .u64 t; cvta.to.shared.u64 t, %1; cvt.u32.u64 %0, t; }" : "=r"(a) : "l"(p));
    return a;
}
__device__ __forceinline__ void cpa16(uint32_t s, const void* g) {
    asm volatile("cp.async.ca.shared.global [%0], [%1], 16;" :: "r"(s), "l"(g));
}
__device__ __forceinline__ void cpcommit() { asm volatile("cp.async.commit_group;"); }
__device__ __forceinline__ void cpwait0() { asm volatile("cp.async.wait_group 0;"); }

// --- pre-split mem (both orientations) ---
__global__ void k_split(const float* __restrict__ mem) {
    int i = blockIdx.x * blockDim.x + threadIdx.x;
    if (i >= NSHARD * MSZ * 32) return;
    {
        int wp = i & 31, m = (i >> 5) & 511, sid = i >> 14;
        const float* src = mem + ((size_t)sid * MSZ + m) * WD + 2 * wp;
        uint32_t h, l;
        bsp2(src[0], src[1], h, l);
        g_mh[i] = h;
        g_ml[i] = l;
    }
    {
        int mp = i & 255, w = (i >> 8) & 63, sid = i >> 14;
        const float* base = mem + (size_t)sid * MSZ * WD;
        uint32_t h, l;
        bsp2(base[(size_t)(2 * mp) * WD + w], base[(size_t)(2 * mp + 1) * WD + w], h, l);
        g_mhT[i] = h;
        g_mlT[i] = l;
    }
}

// --- pre-split Wq: pairs along k ---
__global__ void k_splitw(const float* __restrict__ Wq) {
    int i = blockIdx.x * blockDim.x + threadIdx.x;
    if (i >= NSHARD * (IND / 2) * QO) return;
    int n = i & 255, kp = (i >> 8) % (IND / 2), sid = i / ((IND / 2) * QO);
    const float* base = Wq + (size_t)sid * IND * QO;
    uint32_t h, l;
    bsp2(base[(size_t)(2 * kp) * QO + n], base[(size_t)(2 * kp + 1) * QO + n], h, l);
    g_wh[i] = h;
    g_wl[i] = l;
}

__global__ void k_pe(const float* __restrict__ tab, const float* __restrict__ Wp,
                     const float* __restrict__ bp) {
    __shared__ float ue[E];
    int b = blockIdx.x;
    int t = threadIdx.x;
    int uid = g_uid[b];
    if (t < E) ue[t] = tab[(size_t)uid * E + t];
    __syncthreads();
    float acc = bp[t];
#pragma unroll
    for (int e = 0; e < E; e++) acc += ue[e] * Wp[e * P + t];
    g_pe[b * P + t] = acc;
}

// --- q = concat(x, pe) @ Wq[sid]; bf16 k16 3-pass, pre-split B ---
__global__ __launch_bounds__(256) void k_qgemm(const float* __restrict__ x) {
    extern __shared__ uint32_t qsm[];
    uint32_t* Ah = qsm;                       // [2][64][AQ_STRIDE]
    uint32_t* Al = Ah + 2 * 64 * AQ_STRIDE;
    uint32_t* Bh = Al + 2 * 64 * AQ_STRIDE;   // [2][16][BQ_STRIDE]
    uint32_t* Bl = Bh + 2 * 16 * BQ_STRIDE;

    int b = blockIdx.z;
    int n0 = blockIdx.x * 128, m0 = blockIdx.y * 64;
    int sid = ((unsigned)g_uid[b]) % NSHARD;
    int tid = threadIdx.x;
    int lane = tid & 31, warp = tid >> 5;
    int g = lane >> 2, c = lane & 3;
    int wm = warp & 3, wn = warp >> 2;
    const float* xb = x + ((size_t)b * SS + m0) * INSZ;
    const float* pe = g_pe + b * P;
    const uint32_t* Wh = g_wh + (size_t)sid * (IND / 2) * QO;
    const uint32_t* Wl = g_wl + (size_t)sid * (IND / 2) * QO;
    uint32_t bhb = smem_u32(Bh);
    uint32_t blb = smem_u32(Bl);

    float d[8][4];
#pragma unroll
    for (int i = 0; i < 8; i++)
#pragma unroll
        for (int j = 0; j < 4; j++) d[i][j] = 0.f;

    // staging helpers
    int srow = tid >> 2, sf4 = tid & 3;        // thread -> 2 rows' worth: covers 64x8 f4 in 2 steps
    float4 areg[2];

#define LDA(t)                                                                            \
    do {                                                                                  \
        int k0_ = (t) * 32;                                                               \
        _Pragma("unroll") for (int s = 0; s < 2; s++) {                                   \
            int i = tid + s * 256;                                                        \
            int row = i >> 3, f4 = i & 7;                                                 \
            areg[s] = (k0_ < INSZ) ? *(const float4*)&xb[row * INSZ + k0_ + f4 * 4]       \
                                   : *(const float4*)&pe[k0_ - INSZ + f4 * 4];            \
        }                                                                                 \
    } while (0)

#define STA(buf)                                                                          \
    do {                                                                                  \
        _Pragma("unroll") for (int s = 0; s < 2; s++) {                                   \
            int i = tid + s * 256;                                                        \
            int row = i >> 3, f4 = i & 7;                                                 \
            uint32_t h0, l0, h1, l1;                                                      \
            bsp2(areg[s].x, areg[s].y, h0, l0);                                           \
            bsp2(areg[s].z, areg[s].w, h1, l1);                                           \
            uint32_t o = (buf) * 64 * AQ_STRIDE + row * AQ_STRIDE + f4 * 2;               \
            Ah[o] = h0; Ah[o + 1] = h1;                                                   \
            Al[o] = l0; Al[o + 1] = l1;                                                   \
        }                                                                                 \
    } while (0)

#define LDB(t, buf)                                                                       \
    do {                                                                                  \
        for (int i = tid; i < 512; i += 256) {                                            \
            int kp = i >> 5, n4 = (i & 31) * 4;                                           \
            size_t go = (size_t)((t) * 16 + kp) * QO + n0 + n4;                           \
            uint32_t so = ((buf) * 16 * BQ_STRIDE + kp * BQ_STRIDE + n4) * 4;             \
            cpa16(bhb + so, &Wh[go]);                                                     \
            cpa16(blb + so, &Wl[go]);                                                     \
        }                                                                                 \
    } while (0)

    LDB(0, 0);
    cpcommit();
    LDA(0);
    STA(0);
    cpwait0();
    __syncthreads();

    for (int t = 0; t < 12; t++) {
        int buf = t & 1;
        if (t < 11) {
            LDB(t + 1, buf ^ 1);
            cpcommit();
            LDA(t + 1);
        }
        // compute on buf: 2 k16 steps
#pragma unroll
        for (int ks = 0; ks < 2; ks++) {
            uint32_t ah[4], al[4];
            uint32_t ra = buf * 64 * AQ_STRIDE;
            ah[0] = Ah[ra + (wm * 16 + g) * AQ_STRIDE + ks * 8 + c];
            ah[1] = Ah[ra + (wm * 16 + g + 8) * AQ_STRIDE + ks * 8 + c];
            ah[2] = Ah[ra + (wm * 16 + g) * AQ_STRIDE + ks * 8 + c + 4];
            ah[3] = Ah[ra + (wm * 16 + g + 8) * AQ_STRIDE + ks * 8 + c + 4];
            al[0] = Al[ra + (wm * 16 + g) * AQ_STRIDE + ks * 8 + c];
            al[1] = Al[ra + (wm * 16 + g + 8) * AQ_STRIDE + ks * 8 + c];
            al[2] = Al[ra + (wm * 16 + g) * AQ_STRIDE + ks * 8 + c + 4];
            al[3] = Al[ra + (wm * 16 + g + 8) * AQ_STRIDE + ks * 8 + c + 4];
            uint32_t rb = buf * 16 * BQ_STRIDE;
#pragma unroll
            for (int nt = 0; nt < 8; nt++) {
                int nn = wn * 64 + nt * 8 + g;
                uint32_t bh0 = Bh[rb + (ks * 8 + c) * BQ_STRIDE + nn];
                uint32_t bh1 = Bh[rb + (ks * 8 + c + 4) * BQ_STRIDE + nn];
                uint32_t bl0 = Bl[rb + (ks * 8 + c) * BQ_STRIDE + nn];
                uint32_t bl1 = Bl[rb + (ks * 8 + c + 4) * BQ_STRIDE + nn];
                mmab(d[nt], ah, bh0, bh1);
                mmab(d[nt], ah, bl0, bl1);
                mmab(d[nt], al, bh0, bh1);
            }
        }
        if (t < 11) {
            STA(buf ^ 1);
            cpwait0();
        }
        __syncthreads();
    }

    float* qb = g_q + ((size_t)b * SS + m0) * QO + n0;
#pragma unroll
    for (int nt = 0; nt < 8; nt++) {
        int nn = wn * 64 + nt * 8 + 2 * c;
        float2 v01 = {d[nt][0], d[nt][1]};
        float2 v23 = {d[nt][2], d[nt][3]};
        *(float2*)&qb[(size_t)(wm * 16 + g) * QO + nn] = v01;
        *(float2*)&qb[(size_t)(wm * 16 + g + 8) * QO + nn] = v23;
    }
}

// ---- flash attention (R16, unchanged) ----
__global__ __launch_bounds__(256, 2) void k_attn(float* __restrict__ out) {
    extern __shared__ uint32_t smu[];
    uint32_t* msh = smu;
    uint32_t* msl = msh + 128 * MH_STRIDE;
    uint32_t* mshT = msl + 128 * MH_STRIDE;
    uint32_t* mslT = mshT + 64 * MT_STRIDE;
    float* es = (float*)(mslT + 64 * MT_STRIDE);

    int tid = threadIdx.x;
    int lane = tid & 31, warp = tid >> 5;
    int g = lane >> 2, c = lane & 3;
    int b = blockIdx.y;
    int s0 = blockIdx.x * 32;
    int sid = ((unsigned)g_uid[b]) % NSHARD;
    float* ew = es + warp * (16 * ESP);
    int wrow = warp * 16;

    const uint32_t* Mh = g_mh + (size_t)sid * MSZ * 32;
    const uint32_t* Ml = g_ml + (size_t)sid * MSZ * 32;
    const uint32_t* MhT = g_mhT + (size_t)sid * WD * 256;
    const uint32_t* MlT = g_mlT + (size_t)sid * WD * 256;

    uint32_t ahp[4][4], alp[4][4];
    {
        const float* qsrc = g_q + ((size_t)b * SS + s0) * QO;
        int r0 = wrow + g, r1 = wrow + g + 8;
        const float* qb0 = qsrc + (size_t)(r0 >> 2) * QO + (r0 & 3) * WD;
        const float* qb1 = qsrc + (size_t)(r1 >> 2) * QO + (r1 & 3) * WD;
#pragma unroll
        for (int ks = 0; ks < 4; ks++) {
            float2 x0 = *(const float2*)&qb0[ks * 16 + 2 * c];
            float2 x1 = *(const float2*)&qb1[ks * 16 + 2 * c];
            float2 x2 = *(const float2*)&qb0[ks * 16 + 2 * c + 8];
            float2 x3 = *(const float2*)&qb1[ks * 16 + 2 * c + 8];
            bsp(x0, ahp[ks][0], alp[ks][0]);
            bsp(x1, ahp[ks][1], alp[ks][1]);
            bsp(x2, ahp[ks][2], alp[ks][2]);
            bsp(x3, ahp[ks][3], alp[ks][3]);
        }
    }

    float acc[8][4];
#pragma unroll
    for (int nt = 0; nt < 8; nt++)
#pragma unroll
        for (int j = 0; j < 4; j++) acc[nt][j] = 0.f;
    float mx = -1e30f, sm0 = 0.f, sm1 = 0.f;

    for (int ch = 0; ch < 4; ch++) {
        for (int i = tid; i < 128 * 8; i += 256) {
            int m = i >> 3, q4 = (i & 7) * 4;
            size_t go = ((size_t)ch * 128 + m) * 32 + q4;
            *(uint4*)&msh[m * MH_STRIDE + q4] = *(const uint4*)&Mh[go];
            *(uint4*)&msl[m * MH_STRIDE + q4] = *(const uint4*)&Ml[go];
        }
        for (int i = tid; i < 64 * 16; i += 256) {
            int w = i >> 4, q4 = (i & 15) * 4;
            size_t go = (size_t)w * 256 + ch * 64 + q4;
            *(uint4*)&mshT[w * MT_STRIDE + q4] = *(const uint4*)&MhT[go];
            *(uint4*)&mslT[w * MT_STRIDE + q4] = *(const uint4*)&MlT[go];
        }
        __syncthreads();

        for (int sb = 0; sb < 8; sb++) {
            float e[2][4];
#pragma unroll
            for (int nt2 = 0; nt2 < 2; nt2++) {
                int mc = sb * 16 + nt2 * 8;
                float d0[4] = {0.f, 0.f, 0.f, 0.f};
                float d1[4] = {0.f, 0.f, 0.f, 0.f};
#pragma unroll
                for (int ks = 0; ks < 4; ks += 2) {
                    {
                        const uint32_t* rh = &msh[(mc + g) * MH_STRIDE + ks * 8 + c];
                        const uint32_t* rl = &msl[(mc + g) * MH_STRIDE + ks * 8 + c];
                        mmab(d0, ahp[ks], rh[0], rh[4]);
                        mmab(d0, ahp[ks], rl[0], rl[4]);
                        mmab(d0, alp[ks], rh[0], rh[4]);
                    }
                    {
                        const uint32_t* rh = &msh[(mc + g) * MH_STRIDE + (ks + 1) * 8 + c];
                        const uint32_t* rl = &msl[(mc + g) * MH_STRIDE + (ks + 1) * 8 + c];
                        mmab(d1, ahp[ks + 1], rh[0], rh[4]);
                        mmab(d1, ahp[ks + 1], rl[0], rl[4]);
                        mmab(d1, alp[ks + 1], rh[0], rh[4]);
                    }
                }
#pragma unroll
                for (int j = 0; j < 4; j++) e[nt2][j] = d0[j] + d1[j];
            }
            float m = fmaxf(fmaxf(fmaxf(e[0][0], e[0][1]), fmaxf(e[0][2], e[0][3])),
                            fmaxf(fmaxf(e[1][0], e[1][1]), fmaxf(e[1][2], e[1][3])));
#pragma unroll
            for (int o = 16; o > 0; o >>= 1) m = fmaxf(m, __shfl_xor_sync(0xffffffffu, m, o));
            if (m > mx) {
                float sc = __expf(mx - m);
                sm0 *= sc; sm1 *= sc;
#pragma unroll
                for (int nt = 0; nt < 8; nt++) {
                    acc[nt][0] *= sc; acc[nt][1] *= sc;
                    acc[nt][2] *= sc; acc[nt][3] *= sc;
                }
                mx = m;
            }
#pragma unroll
            for (int nt2 = 0; nt2 < 2; nt2++) {
                float e0 = __expf(e[nt2][0] - mx);
                float e1 = __expf(e[nt2][1] - mx);
                float e2 = __expf(e[nt2][2] - mx);
                float e3 = __expf(e[nt2][3] - mx);
                sm0 += e0 + e1; sm1 += e2 + e3;
                int col = nt2 * 8 + 2 * c;
                float2 v01 = {e0, e1};
                float2 v23 = {e2, e3};
                *(float2*)&ew[g * ESP + col] = v01;
                *(float2*)&ew[(g + 8) * ESP + col] = v23;
            }
            __syncwarp();
            {
                uint32_t awh[4], awl[4];
                float2 w0 = *(const float2*)&ew[g * ESP + 2 * c];
                float2 w1 = *(const float2*)&ew[(g + 8) * ESP + 2 * c];
                float2 w2 = *(const float2*)&ew[g * ESP + 2 * c + 8];
                float2 w3 = *(const float2*)&ew[(g + 8) * ESP + 2 * c + 8];
                bsp(w0, awh[0], awl[0]);
                bsp(w1, awh[1], awl[1]);
                bsp(w2, awh[2], awl[2]);
                bsp(w3, awh[3], awl[3]);
#pragma unroll
                for (int nt = 0; nt < 8; nt++) {
                    int w0c = nt * 8 + g;
                    const uint32_t* rh = &mshT[w0c * MT_STRIDE + sb * 8 + c];
                    const uint32_t* rl = &mslT[w0c * MT_STRIDE + sb * 8 + c];
                    mmab(acc[nt], awh, rh[0], rh[4]);
                    mmab(acc[nt], awh, rl[0], rl[4]);
                    mmab(acc[nt], awl, rh[0], rh[4]);
                }
            }
            __syncwarp();
        }
        __syncthreads();
    }

    sm0 += __shfl_xor_sync(0xffffffffu, sm0, 1);
    sm0 += __shfl_xor_sync(0xffffffffu, sm0, 2);
    sm1 += __shfl_xor_sync(0xffffffffu, sm1, 1);
    sm1 += __shfl_xor_sync(0xffffffffu, sm1, 2);
    float inv0 = 1.f / sm0, inv1 = 1.f / sm1;
    float* ob = out + ((size_t)b * 512 + s0 * 4) * WD;
#pragma unroll
    for (int nt = 0; nt < 8; nt++) {
        int col = nt * 8 + 2 * c;
        float2 v01 = {acc[nt][0] * inv0, acc[nt][1] * inv0};
        float2 v23 = {acc[nt][2] * inv1, acc[nt][3] * inv1};
        *(float2*)&ob[(size_t)(wrow + g) * WD + col] = v01;
        *(float2*)&ob[(size_t)(wrow + g + 8) * WD + col] = v23;
    }

    if (b == BB - 1) {
        float* fs = out + (size_t)BB * SS * RR * WD;
        for (int ch = 0; ch < 4; ch++) {
            for (int i = tid; i < 128 * 8; i += 256) {
                int m = i >> 3, q4 = (i & 7) * 4;
                size_t go = ((size_t)ch * 128 + m) * 32 + q4;
                *(uint4*)&msh[m * MH_STRIDE + q4] = *(const uint4*)&Mh[go];
                *(uint4*)&msl[m * MH_STRIDE + q4] = *(const uint4*)&Ml[go];
            }
            __syncthreads();
            for (int sb = 0; sb < 8; sb++) {
#pragma unroll
                for (int nt2 = 0; nt2 < 2; nt2++) {
                    int mc = sb * 16 + nt2 * 8;
                    float d[4] = {0.f, 0.f, 0.f, 0.f};
#pragma unroll
                    for (int ks = 0; ks < 4; ks++) {
                        const uint32_t* rh = &msh[(mc + g) * MH_STRIDE + ks * 8 + c];
                        const uint32_t* rl = &msl[(mc + g) * MH_STRIDE + ks * 8 + c];
                        mmab(d, ahp[ks], rh[0], rh[4]);
                        mmab(d, ahp[ks], rl[0], rl[4]);
                        mmab(d, alp[ks], rh[0], rh[4]);
                    }
                    int col = ch * 128 + mc + 2 * c;
                    float2 v01 = {__expf(d[0] - mx) * inv0, __expf(d[1] - mx) * inv0};
                    float2 v23 = {__expf(d[2] - mx) * inv1, __expf(d[3] - mx) * inv1};
                    *(float2*)&fs[(size_t)(s0 * 4 + wrow + g) * MSZ + col] = v01;
                    *(float2*)&fs[(size_t)(s0 * 4 + wrow + g + 8) * MSZ + col] = v23;
                }
            }
            __syncthreads();
        }
    }
}

extern "C" void kernel_launch(void* const* d_in, const int* in_sizes, int n_in,
                              void* d_out, int out_size) {
    const float* x = (const float*)d_in[0];
    const int* uid = (const int*)d_in[1];
    const float* tab = (const float*)d_in[2];
    const float* Wp = (const float*)d_in[3];
    const float* bp = (const float*)d_in[4];
    const float* Wq = (const float*)d_in[5];
    const float* memp = (const float*)d_in[6];
    float* out = (float*)d_out;

    k_uid<<<1, 256>>>(uid);
    k_split<<<(NSHARD * MSZ * 32 + 255) / 256, 256>>>(memp);
    k_splitw<<<(NSHARD * (IND / 2) * QO + 255) / 256, 256>>>(Wq);
    k_pe<<<BB, 128>>>(tab, Wp, bp);

    const int qg_smem = (2 * 64 * AQ_STRIDE * 2 + 2 * 16 * BQ_STRIDE * 2) * 4;
    cudaFuncSetAttribute(k_qgemm, cudaFuncAttributeMaxDynamicSharedMemorySize, qg_smem);
    dim3 g2(2, 2, BB);
    k_qgemm<<<g2, 256, qg_smem>>>(x);

    const int at_smem = (2 * 128 * MH_STRIDE + 2 * 64 * MT_STRIDE + 8 * 16 * ESP) * 4;
    cudaFuncSetAttribute(k_attn, cudaFuncAttributeMaxDynamicSharedMemorySize, at_smem);
    dim3 g3(4, BB);
    k_attn<<<g3, 256, at_smem>>>(out);
}